// round 3
// baseline (speedup 1.0000x reference)
#include <cuda_runtime.h>
#include <math.h>

#define NROWS 4096
#define NW 128          // adjacency bitmask words per row (4096/32)
#define HID 64
#define ALPHA 0.2f
#define BRR 128         // attention rows per block
#define BM 32           // attention m-chunk
#define HSW 272         // swizzled h-tile row pitch in bytes

// ---------------- device scratch ----------------
__device__ unsigned int g_adjbits[NROWS * NW];       // 2 MB packed adjacency
__device__ float g_h[4 * NROWS * HID];               // per-layer head features (4 MB)
__device__ float g_el[4 * NROWS];
__device__ float g_er[4 * NROWS];
__device__ unsigned int g_emax_u[4];                 // ordered-uint per-head max(e_r)
__device__ float g_buf[NROWS * 256];                 // inter-layer activations (4 MB)
__device__ float g_pnum[32 * 4 * BRR * HID];         // layer-2 partial numerators
__device__ float g_pden[32 * 4 * BRR];               // layer-2 partial denominators

// ---------------- helpers ----------------
__device__ __forceinline__ unsigned long long pack2(float x) {
    unsigned long long r;
    asm("mov.b64 %0, {%1, %1};" : "=l"(r) : "f"(x));
    return r;
}
__device__ __forceinline__ void fma2(unsigned long long& d, unsigned long long a, unsigned long long b) {
    asm("fma.rn.f32x2 %0, %1, %2, %0;" : "+l"(d) : "l"(a), "l"(b));
}
__device__ __forceinline__ float2 unpack2(unsigned long long v) {
    float2 f;
    asm("mov.b64 {%0, %1}, %2;" : "=f"(f.x), "=f"(f.y) : "l"(v));
    return f;
}
__device__ __forceinline__ unsigned f2ord(float f) {
    unsigned u = __float_as_uint(f);
    return (u & 0x80000000u) ? ~u : (u | 0x80000000u);
}
__device__ __forceinline__ float ord2f(unsigned u) {
    return (u & 0x80000000u) ? __uint_as_float(u ^ 0x80000000u) : __uint_as_float(~u);
}

// ---------------- 1. pack adjacency into bitmask ----------------
__global__ void pack_adj_kernel(const int* __restrict__ adj) {
    int n = blockIdx.x;
    int warp = threadIdx.x >> 5, lane = threadIdx.x & 31;
    const int* row = adj + (size_t)n * NROWS;
    #pragma unroll 4
    for (int w = warp * 32; w < warp * 32 + 32; w++) {
        int v = row[w * 32 + lane];
        unsigned int bits = __ballot_sync(0xffffffffu, v > 0);
        if (lane == 0) g_adjbits[n * NW + w] = bits;
    }
}

// ---------------- 2. feature GEMM: g_h[head][n][o] = X @ W[head] ----------------
__global__ __launch_bounds__(256) void gemm_kernel(const float* __restrict__ Xext,
                                                   const float* __restrict__ W,
                                                   int D, int useBuf) {
    if (blockIdx.x == 0 && blockIdx.y == 0 && threadIdx.x < 4) g_emax_u[threadIdx.x] = 0u;

    const float* __restrict__ X = useBuf ? (const float*)g_buf : Xext;
    const int head = blockIdx.y;
    const int r0 = blockIdx.x * 64;
    const int tid = threadIdx.x;
    __shared__ __align__(16) float Xs[64][33];
    __shared__ __align__(16) float Ws[32][64];
    float acc[4][4];
    #pragma unroll
    for (int r = 0; r < 4; r++)
        #pragma unroll
        for (int c = 0; c < 4; c++) acc[r][c] = 0.f;

    const int fr = tid >> 4, cg = tid & 15;
    const float* Wh = W + (size_t)head * D * HID;

    for (int d0 = 0; d0 < D; d0 += 32) {
        {
            int j = tid & 31, n0 = (tid >> 5) * 8;
            #pragma unroll
            for (int i = 0; i < 8; i++)
                Xs[n0 + i][j] = X[(size_t)(r0 + n0 + i) * D + d0 + j];
        }
        {
            int o = tid & 63, j0 = (tid >> 6) * 8;
            #pragma unroll
            for (int i = 0; i < 8; i++)
                Ws[j0 + i][o] = Wh[(size_t)(d0 + j0 + i) * HID + o];
        }
        __syncthreads();
        #pragma unroll
        for (int k = 0; k < 32; k++) {
            float4 wv = *(const float4*)&Ws[k][cg * 4];
            float x0 = Xs[fr * 4 + 0][k];
            float x1 = Xs[fr * 4 + 1][k];
            float x2 = Xs[fr * 4 + 2][k];
            float x3 = Xs[fr * 4 + 3][k];
            acc[0][0] += x0 * wv.x; acc[0][1] += x0 * wv.y; acc[0][2] += x0 * wv.z; acc[0][3] += x0 * wv.w;
            acc[1][0] += x1 * wv.x; acc[1][1] += x1 * wv.y; acc[1][2] += x1 * wv.z; acc[1][3] += x1 * wv.w;
            acc[2][0] += x2 * wv.x; acc[2][1] += x2 * wv.y; acc[2][2] += x2 * wv.z; acc[2][3] += x2 * wv.w;
            acc[3][0] += x3 * wv.x; acc[3][1] += x3 * wv.y; acc[3][2] += x3 * wv.z; acc[3][3] += x3 * wv.w;
        }
        __syncthreads();
    }
    float* hp = g_h + ((size_t)head * NROWS + r0) * HID;
    #pragma unroll
    for (int r = 0; r < 4; r++) {
        *(float4*)&hp[(size_t)(fr * 4 + r) * HID + cg * 4] =
            make_float4(acc[r][0], acc[r][1], acc[r][2], acc[r][3]);
    }
}

// ---------------- 3. e_l / e_r per (head, node), fused per-head max(e_r) ----------------
__global__ void compute_e_kernel(const float* __restrict__ a, int H) {
    int gw = (blockIdx.x * blockDim.x + threadIdx.x) >> 5;
    int lane = threadIdx.x & 31;
    int head = gw >> 12;
    int n = gw & (NROWS - 1);
    __shared__ float wmax[8];
    const float* hp = g_h + ((size_t)head * NROWS + n) * HID;
    const float* ah = a + head * 2 * HID;
    float sl = 0.f, sr = 0.f;
    #pragma unroll
    for (int i = lane; i < HID; i += 32) {
        float hv = hp[i];
        sl += hv * ah[i];
        sr += hv * ah[HID + i];
    }
    #pragma unroll
    for (int off = 16; off; off >>= 1) {
        sl += __shfl_xor_sync(0xffffffffu, sl, off);
        sr += __shfl_xor_sync(0xffffffffu, sr, off);
    }
    if (lane == 0) {
        g_el[head * NROWS + n] = sl;
        g_er[head * NROWS + n] = sr;
        wmax[threadIdx.x >> 5] = sr;
    }
    __syncthreads();
    if (threadIdx.x == 0) {
        float m = wmax[0];
        #pragma unroll
        for (int i = 1; i < 8; i++) m = fmaxf(m, wmax[i]);
        atomicMax(&g_emax_u[head], f2ord(m));
    }
}

// ---------------- 4. fused masked-softmax attention ----------------
// 128 threads, 128x64 tile, 8x8 per thread, swizzled h tile, f32x2 FMAs.
__global__ __launch_bounds__(128) void attn_kernel(float* __restrict__ extOut,
                                                   int ostride, int doElu,
                                                   int toBuf, int partial) {
    const int head = blockIdx.y;
    const int r0 = blockIdx.x * BRR;
    const int z = blockIdx.z;
    const int msplit = gridDim.z;
    const int mlen = NROWS / msplit;
    const int mstart = z * mlen;
    const int tid = threadIdx.x;

    __shared__ __align__(16) char hs[BM * HSW];       // swizzled h tile, 8.5 KB
    __shared__ __align__(16) float ps[BM][BRR];       // 16 KB
    __shared__ __align__(16) float ers[NROWS];        // (slice) 16 KB max
    __shared__ float dsum[BRR];

    // stage e_r slice (coalesced)
    {
        const float4* er4 = (const float4*)(g_er + head * NROWS + mstart);
        float4* d4 = (float4*)ers;
        for (int i = tid; i < mlen / 4; i += 128) d4[i] = er4[i];
    }

    const float el = g_el[head * NROWS + r0 + tid];   // score-gen: thread owns row tid
    const float emax = ord2f(g_emax_u[head]);
    float M = el + emax;
    M = fmaxf(M, ALPHA * M);       // lrelu of an upper bound: all exponents <= 0
    float dacc = 0.f;

    const int fr = tid >> 3;       // 16 row-groups x 8 rows
    const int cg = tid & 7;        // 8 col-groups x 8 cols
    const int hoff = cg * 32 + ((cg & 4) ? 16 : 0);   // swizzled byte offset of my 8 cols

    unsigned long long acc[8][4];
    #pragma unroll
    for (int r = 0; r < 8; r++)
        #pragma unroll
        for (int c = 0; c < 4; c++) acc[r][c] = 0ULL;

    const float* hb = g_h + (size_t)head * NROWS * HID;
    const unsigned int* aw = g_adjbits + (size_t)(r0 + tid) * NW;

    __syncthreads();  // ers ready

    for (int m0 = mstart; m0 < mstart + mlen; m0 += BM) {
        // stage h tile [BM][64] with swizzle (512 float4, 4 per thread)
        #pragma unroll
        for (int i = 0; i < 4; i++) {
            int e = tid + i * 128;
            int rr = e >> 4, b = e & 15;
            int phys = rr * HSW + (b >> 1) * 32 + ((b & 8) ? 16 : 0) + (b & 1) * 16;
            *(float4*)(hs + phys) = *(const float4*)&hb[(size_t)(m0 + rr) * HID + b * 4];
        }
        // score-gen: 32 p-values for my row
        unsigned int word = aw[m0 >> 5];
        const float* erc = ers + (m0 - mstart);
        #pragma unroll
        for (int j = 0; j < 32; j++) {
            float s = el + erc[j];
            s = fmaxf(s, ALPHA * s);                 // leaky relu
            float p = 0.f;
            if ((word >> j) & 1u) p = __expf(s - M);
            dacc += p;
            ps[j][tid] = p;
        }
        __syncthreads();
        // P @ h: 4 LDS.128 + 8 packs + 32 fma2 per k
        #pragma unroll
        for (int k = 0; k < BM; k++) {
            float4 pA = *(const float4*)&ps[k][fr * 8];
            float4 pB = *(const float4*)&ps[k][fr * 8 + 4];
            const char* hk = hs + k * HSW + hoff;
            ulonglong2 h0 = *(const ulonglong2*)hk;
            ulonglong2 h1 = *(const ulonglong2*)(hk + 16);
            unsigned long long pp;
            pp = pack2(pA.x);
            fma2(acc[0][0], pp, h0.x); fma2(acc[0][1], pp, h0.y);
            fma2(acc[0][2], pp, h1.x); fma2(acc[0][3], pp, h1.y);
            pp = pack2(pA.y);
            fma2(acc[1][0], pp, h0.x); fma2(acc[1][1], pp, h0.y);
            fma2(acc[1][2], pp, h1.x); fma2(acc[1][3], pp, h1.y);
            pp = pack2(pA.z);
            fma2(acc[2][0], pp, h0.x); fma2(acc[2][1], pp, h0.y);
            fma2(acc[2][2], pp, h1.x); fma2(acc[2][3], pp, h1.y);
            pp = pack2(pA.w);
            fma2(acc[3][0], pp, h0.x); fma2(acc[3][1], pp, h0.y);
            fma2(acc[3][2], pp, h1.x); fma2(acc[3][3], pp, h1.y);
            pp = pack2(pB.x);
            fma2(acc[4][0], pp, h0.x); fma2(acc[4][1], pp, h0.y);
            fma2(acc[4][2], pp, h1.x); fma2(acc[4][3], pp, h1.y);
            pp = pack2(pB.y);
            fma2(acc[5][0], pp, h0.x); fma2(acc[5][1], pp, h0.y);
            fma2(acc[5][2], pp, h1.x); fma2(acc[5][3], pp, h1.y);
            pp = pack2(pB.z);
            fma2(acc[6][0], pp, h0.x); fma2(acc[6][1], pp, h0.y);
            fma2(acc[6][2], pp, h1.x); fma2(acc[6][3], pp, h1.y);
            pp = pack2(pB.w);
            fma2(acc[7][0], pp, h0.x); fma2(acc[7][1], pp, h0.y);
            fma2(acc[7][2], pp, h1.x); fma2(acc[7][3], pp, h1.y);
        }
        __syncthreads();
    }

    dsum[tid] = dacc;
    __syncthreads();

    if (!partial) {
        float* obase = toBuf ? g_buf : extOut;
        #pragma unroll
        for (int r = 0; r < 8; r++) {
            int ri = fr * 8 + r;
            float inv = 1.0f / dsum[ri];
            float2 v0 = unpack2(acc[r][0]);
            float2 v1 = unpack2(acc[r][1]);
            float2 v2 = unpack2(acc[r][2]);
            float2 v3 = unpack2(acc[r][3]);
            float v[8] = {v0.x, v0.y, v1.x, v1.y, v2.x, v2.y, v3.x, v3.y};
            #pragma unroll
            for (int i = 0; i < 8; i++) {
                float t = v[i] * inv;
                if (doElu) t = (t > 0.f) ? t : expm1f(t);
                v[i] = t;
            }
            float* op = obase + (size_t)(r0 + ri) * ostride + head * HID + cg * 8;
            *(float4*)op = make_float4(v[0], v[1], v[2], v[3]);
            *(float4*)(op + 4) = make_float4(v[4], v[5], v[6], v[7]);
        }
    } else {
        float* np = g_pnum + ((size_t)blockIdx.x * msplit + z) * (BRR * HID);
        #pragma unroll
        for (int r = 0; r < 8; r++) {
            int ri = fr * 8 + r;
            float2 v0 = unpack2(acc[r][0]);
            float2 v1 = unpack2(acc[r][1]);
            float2 v2 = unpack2(acc[r][2]);
            float2 v3 = unpack2(acc[r][3]);
            float* op = np + ri * HID + cg * 8;
            *(float4*)op = make_float4(v0.x, v0.y, v1.x, v1.y);
            *(float4*)(op + 4) = make_float4(v2.x, v2.y, v3.x, v3.y);
        }
        g_pden[((size_t)blockIdx.x * msplit + z) * BRR + tid] = dacc;
    }
}

// ---------------- 5. combine layer-2 partials ----------------
__global__ void combine_kernel(float* __restrict__ out) {
    int b = blockIdx.x;   // 32 row-blocks
    for (int idx = threadIdx.x; idx < BRR * HID; idx += 256) {
        int row = idx >> 6;
        float num = 0.f, den = 0.f;
        #pragma unroll
        for (int zz = 0; zz < 4; zz++) {
            num += g_pnum[((size_t)b * 4 + zz) * (BRR * HID) + idx];
            den += g_pden[((size_t)b * 4 + zz) * BRR + row];
        }
        out[(size_t)(b * BRR + row) * HID + (idx & 63)] = num / den;
    }
}

// ---------------- launch ----------------
extern "C" void kernel_launch(void* const* d_in, const int* in_sizes, int n_in,
                              void* d_out, int out_size) {
    const float* x   = (const float*)d_in[0];
    const int*   adj = (const int*)d_in[1];
    const float* W0  = (const float*)d_in[2];
    const float* a0  = (const float*)d_in[3];
    const float* W1  = (const float*)d_in[4];
    const float* a1  = (const float*)d_in[5];
    const float* W2  = (const float*)d_in[6];
    const float* a2  = (const float*)d_in[7];
    float* out = (float*)d_out;

    pack_adj_kernel<<<NROWS, 128>>>(adj);

    // layer 0: D=128, H=4, input = x, output -> g_buf (ELU)
    gemm_kernel<<<dim3(64, 4), 256>>>(x, W0, 128, 0);
    compute_e_kernel<<<4 * 512, 256>>>(a0, 4);
    attn_kernel<<<dim3(32, 4, 1), 128>>>(nullptr, 256, 1, 1, 0);

    // layer 1: D=256, H=4, input = g_buf, output -> g_buf (ELU)
    gemm_kernel<<<dim3(64, 4), 256>>>(nullptr, W1, 256, 1);
    compute_e_kernel<<<4 * 512, 256>>>(a1, 4);
    attn_kernel<<<dim3(32, 4, 1), 128>>>(nullptr, 256, 1, 1, 0);

    // layer 2: D=256, H=1, input = g_buf, output -> d_out (no ELU), m-split=4
    gemm_kernel<<<dim3(64, 1), 256>>>(nullptr, W2, 256, 1);
    compute_e_kernel<<<512, 256>>>(a2, 1);
    attn_kernel<<<dim3(32, 1, 4), 128>>>(nullptr, 0, 0, 0, 1);
    combine_kernel<<<32, 256>>>(out);
}

// round 4
// speedup vs baseline: 1.4522x; 1.4522x over previous
#include <cuda_runtime.h>
#include <math.h>

#define NROWS 4096
#define NW 128          // adjacency bitmask words per row
#define HID 64
#define ALPHA 0.2f
#define BRR 128         // attention rows per block
#define BM 32           // attention m-chunk

// ---------------- device scratch ----------------
__device__ unsigned int g_adjbits[NROWS * NW];       // 2 MB packed adjacency
__device__ float g_h[4 * NROWS * HID];               // per-layer head features (4 MB)
__device__ float g_el[4 * NROWS];
__device__ float g_er[4 * NROWS];
__device__ unsigned int g_emax_u[4];                 // ordered-uint per-head max(e_r)
__device__ float g_buf[NROWS * 256];                 // inter-layer activations (4 MB)
__device__ float g_pnum[32 * 4 * 2 * BRR * HID];     // partial numerators (16 MB)
__device__ float g_pden[32 * 4 * 2 * BRR];           // partial denominators

// ---------------- helpers ----------------
__device__ __forceinline__ unsigned long long pack2(float x) {
    unsigned long long r;
    asm("mov.b64 %0, {%1, %1};" : "=l"(r) : "f"(x));
    return r;
}
__device__ __forceinline__ void fma2(unsigned long long& d, unsigned long long a, unsigned long long b) {
    asm("fma.rn.f32x2 %0, %1, %2, %0;" : "+l"(d) : "l"(a), "l"(b));
}
__device__ __forceinline__ float2 unpack2(unsigned long long v) {
    float2 f;
    asm("mov.b64 {%0, %1}, %2;" : "=f"(f.x), "=f"(f.y) : "l"(v));
    return f;
}
__device__ __forceinline__ unsigned f2ord(float f) {
    unsigned u = __float_as_uint(f);
    return (u & 0x80000000u) ? ~u : (u | 0x80000000u);
}
__device__ __forceinline__ float ord2f(unsigned u) {
    return (u & 0x80000000u) ? __uint_as_float(u ^ 0x80000000u) : __uint_as_float(~u);
}

// ---------------- 1. pack adjacency into bitmask ----------------
__global__ void pack_adj_kernel(const int* __restrict__ adj) {
    int n = blockIdx.x;
    int warp = threadIdx.x >> 5, lane = threadIdx.x & 31;
    const int* row = adj + (size_t)n * NROWS;
    #pragma unroll 4
    for (int w = warp * 32; w < warp * 32 + 32; w++) {
        int v = row[w * 32 + lane];
        unsigned int bits = __ballot_sync(0xffffffffu, v > 0);
        if (lane == 0) g_adjbits[n * NW + w] = bits;
    }
}

// ---------------- 2. feature GEMM: g_h[head][n][o] = X @ W[head] ----------------
__global__ __launch_bounds__(256) void gemm_kernel(const float* __restrict__ Xext,
                                                   const float* __restrict__ W,
                                                   int D, int useBuf) {
    if (blockIdx.x == 0 && blockIdx.y == 0 && threadIdx.x < 4) g_emax_u[threadIdx.x] = 0u;

    const float* __restrict__ X = useBuf ? (const float*)g_buf : Xext;
    const int head = blockIdx.y;
    const int r0 = blockIdx.x * 64;
    const int tid = threadIdx.x;
    __shared__ __align__(16) float Xs[64][33];
    __shared__ __align__(16) float Ws[32][64];
    float acc[4][4];
    #pragma unroll
    for (int r = 0; r < 4; r++)
        #pragma unroll
        for (int c = 0; c < 4; c++) acc[r][c] = 0.f;

    const int fr = tid >> 4, cg = tid & 15;
    const float* Wh = W + (size_t)head * D * HID;

    for (int d0 = 0; d0 < D; d0 += 32) {
        {
            int j = tid & 31, n0 = (tid >> 5) * 8;
            #pragma unroll
            for (int i = 0; i < 8; i++)
                Xs[n0 + i][j] = X[(size_t)(r0 + n0 + i) * D + d0 + j];
        }
        {
            int o = tid & 63, j0 = (tid >> 6) * 8;
            #pragma unroll
            for (int i = 0; i < 8; i++)
                Ws[j0 + i][o] = Wh[(size_t)(d0 + j0 + i) * HID + o];
        }
        __syncthreads();
        #pragma unroll
        for (int k = 0; k < 32; k++) {
            float4 wv = *(const float4*)&Ws[k][cg * 4];
            float x0 = Xs[fr * 4 + 0][k];
            float x1 = Xs[fr * 4 + 1][k];
            float x2 = Xs[fr * 4 + 2][k];
            float x3 = Xs[fr * 4 + 3][k];
            acc[0][0] += x0 * wv.x; acc[0][1] += x0 * wv.y; acc[0][2] += x0 * wv.z; acc[0][3] += x0 * wv.w;
            acc[1][0] += x1 * wv.x; acc[1][1] += x1 * wv.y; acc[1][2] += x1 * wv.z; acc[1][3] += x1 * wv.w;
            acc[2][0] += x2 * wv.x; acc[2][1] += x2 * wv.y; acc[2][2] += x2 * wv.z; acc[2][3] += x2 * wv.w;
            acc[3][0] += x3 * wv.x; acc[3][1] += x3 * wv.y; acc[3][2] += x3 * wv.z; acc[3][3] += x3 * wv.w;
        }
        __syncthreads();
    }
    float* hp = g_h + ((size_t)head * NROWS + r0) * HID;
    #pragma unroll
    for (int r = 0; r < 4; r++) {
        *(float4*)&hp[(size_t)(fr * 4 + r) * HID + cg * 4] =
            make_float4(acc[r][0], acc[r][1], acc[r][2], acc[r][3]);
    }
}

// ---------------- 3. e_l / e_r per (head, node), fused per-head max(e_r) ----------------
__global__ void compute_e_kernel(const float* __restrict__ a, int H) {
    int gw = (blockIdx.x * blockDim.x + threadIdx.x) >> 5;
    int lane = threadIdx.x & 31;
    int head = gw >> 12;
    int n = gw & (NROWS - 1);
    __shared__ float wmax[8];
    const float* hp = g_h + ((size_t)head * NROWS + n) * HID;
    const float* ah = a + head * 2 * HID;
    float sl = 0.f, sr = 0.f;
    #pragma unroll
    for (int i = lane; i < HID; i += 32) {
        float hv = hp[i];
        sl += hv * ah[i];
        sr += hv * ah[HID + i];
    }
    #pragma unroll
    for (int off = 16; off; off >>= 1) {
        sl += __shfl_xor_sync(0xffffffffu, sl, off);
        sr += __shfl_xor_sync(0xffffffffu, sr, off);
    }
    if (lane == 0) {
        g_el[head * NROWS + n] = sl;
        g_er[head * NROWS + n] = sr;
        wmax[threadIdx.x >> 5] = sr;
    }
    __syncthreads();
    if (threadIdx.x == 0) {
        float m = wmax[0];
        #pragma unroll
        for (int i = 1; i < 8; i++) m = fmaxf(m, wmax[i]);
        atomicMax(&g_emax_u[head], f2ord(m));
    }
}

// ---------------- 4. fused masked-softmax attention (always writes partials) ----------------
// 256 threads, 128x64 tile, 8 rows x 4 cols per thread, f32x2 FMAs.
__global__ __launch_bounds__(256, 2) void attn_kernel() {
    const int head = blockIdx.y;
    const int r0 = blockIdx.x * BRR;
    const int z = blockIdx.z;
    const int msplit = gridDim.z;
    const int mlen = NROWS / msplit;
    const int mstart = z * mlen;
    const int tid = threadIdx.x;

    __shared__ __align__(16) float hs[BM][HID];       // 8 KB
    __shared__ __align__(16) float ps[BM][BRR];       // 16 KB
    __shared__ __align__(16) float ers[2048];         // 8 KB max slice
    __shared__ float dsum2[2][BRR];
    __shared__ float dsum[BRR];

    // stage e_r slice (coalesced)
    {
        const float4* er4 = (const float4*)(g_er + head * NROWS + mstart);
        float4* d4 = (float4*)ers;
        for (int i = tid; i < mlen / 4; i += 256) d4[i] = er4[i];
    }

    const int row = tid & 127;     // score-gen row
    const int sub = tid >> 7;      // score-gen m sub-range (16 values each)
    const float el = g_el[head * NROWS + r0 + row];
    const float emax = ord2f(g_emax_u[head]);
    float M = el + emax;
    M = fmaxf(M, ALPHA * M);       // lrelu of an upper bound: all exponents <= 0
    float dacc = 0.f;

    const int fr = tid >> 4;       // 16 row-groups x 8 rows
    const int cg = tid & 15;       // 16 col-groups x 4 cols

    unsigned long long acc[8][2];
    #pragma unroll
    for (int r = 0; r < 8; r++) { acc[r][0] = 0ULL; acc[r][1] = 0ULL; }

    const float* hb = g_h + (size_t)head * NROWS * HID;
    const unsigned int* aw = g_adjbits + (size_t)(r0 + row) * NW;

    __syncthreads();  // ers ready

    for (int m0 = mstart; m0 < mstart + mlen; m0 += BM) {
        // stage h tile [BM][64] (512 float4, 2 per thread)
        #pragma unroll
        for (int i = 0; i < 2; i++) {
            int e = tid + i * 256;
            int rr = e >> 4, c4 = (e & 15) << 2;
            *(float4*)&hs[rr][c4] = *(const float4*)&hb[(size_t)(m0 + rr) * HID + c4];
        }
        // score-gen: 16 p-values for (row, sub)
        unsigned int word = aw[m0 >> 5];
        const float* erc = ers + (m0 - mstart) + sub * 16;
        const int mb = sub * 16;
        #pragma unroll
        for (int j = 0; j < 16; j++) {
            float s = el + erc[j];
            s = fmaxf(s, ALPHA * s);                 // leaky relu
            float p = 0.f;
            if ((word >> (mb + j)) & 1u) p = __expf(s - M);
            dacc += p;
            ps[mb + j][row] = p;
        }
        __syncthreads();
        // P @ h: 3 LDS.128 + 8 packs + 16 fma2 per k
        #pragma unroll
        for (int k = 0; k < BM; k++) {
            float4 pA = *(const float4*)&ps[k][fr * 8];
            float4 pB = *(const float4*)&ps[k][fr * 8 + 4];
            ulonglong2 hv = *(const ulonglong2*)&hs[k][cg * 4];
            unsigned long long pp;
            pp = pack2(pA.x); fma2(acc[0][0], pp, hv.x); fma2(acc[0][1], pp, hv.y);
            pp = pack2(pA.y); fma2(acc[1][0], pp, hv.x); fma2(acc[1][1], pp, hv.y);
            pp = pack2(pA.z); fma2(acc[2][0], pp, hv.x); fma2(acc[2][1], pp, hv.y);
            pp = pack2(pA.w); fma2(acc[3][0], pp, hv.x); fma2(acc[3][1], pp, hv.y);
            pp = pack2(pB.x); fma2(acc[4][0], pp, hv.x); fma2(acc[4][1], pp, hv.y);
            pp = pack2(pB.y); fma2(acc[5][0], pp, hv.x); fma2(acc[5][1], pp, hv.y);
            pp = pack2(pB.z); fma2(acc[6][0], pp, hv.x); fma2(acc[6][1], pp, hv.y);
            pp = pack2(pB.w); fma2(acc[7][0], pp, hv.x); fma2(acc[7][1], pp, hv.y);
        }
        __syncthreads();
    }

    dsum2[sub][row] = dacc;
    __syncthreads();
    if (tid < BRR) dsum[tid] = dsum2[0][tid] + dsum2[1][tid];
    __syncthreads();

    const int pidx = (blockIdx.x * gridDim.y + head) * msplit + z;
    float* np = g_pnum + (size_t)pidx * (BRR * HID);
    #pragma unroll
    for (int r = 0; r < 8; r++) {
        int ri = fr * 8 + r;
        float2 v0 = unpack2(acc[r][0]);
        float2 v1 = unpack2(acc[r][1]);
        *(float4*)(np + ri * HID + cg * 4) = make_float4(v0.x, v0.y, v1.x, v1.y);
    }
    if (tid < BRR) g_pden[(size_t)pidx * BRR + tid] = dsum[tid];
}

// ---------------- 5. combine partials -> dest (divide + optional ELU) ----------------
__global__ void combine_kernel(float* __restrict__ dest, int msplit,
                               int ostride, int doElu, int useBuf) {
    const int rb = blockIdx.x, head = blockIdx.y, H = gridDim.y;
    float* obase = useBuf ? g_buf : dest;
    const int base = (rb * H + head) * msplit;
    for (int idx = threadIdx.x; idx < BRR * HID; idx += 256) {
        int row = idx >> 6;
        float num = 0.f, den = 0.f;
        for (int zz = 0; zz < msplit; zz++) {
            num += g_pnum[(size_t)(base + zz) * (BRR * HID) + idx];
            den += g_pden[(size_t)(base + zz) * BRR + row];
        }
        float t = num / den;
        if (doElu) t = (t > 0.f) ? t : expm1f(t);
        obase[(size_t)(rb * BRR + row) * ostride + head * HID + (idx & 63)] = t;
    }
}

// ---------------- launch ----------------
extern "C" void kernel_launch(void* const* d_in, const int* in_sizes, int n_in,
                              void* d_out, int out_size) {
    const float* x   = (const float*)d_in[0];
    const int*   adj = (const int*)d_in[1];
    const float* W0  = (const float*)d_in[2];
    const float* a0  = (const float*)d_in[3];
    const float* W1  = (const float*)d_in[4];
    const float* a1  = (const float*)d_in[5];
    const float* W2  = (const float*)d_in[6];
    const float* a2  = (const float*)d_in[7];
    float* out = (float*)d_out;

    pack_adj_kernel<<<NROWS, 128>>>(adj);

    // layer 0: D=128, H=4, msplit=2
    gemm_kernel<<<dim3(64, 4), 256>>>(x, W0, 128, 0);
    compute_e_kernel<<<4 * 512, 256>>>(a0, 4);
    attn_kernel<<<dim3(32, 4, 2), 256>>>();
    combine_kernel<<<dim3(32, 4), 256>>>(nullptr, 2, 256, 1, 1);

    // layer 1: D=256, H=4, msplit=2
    gemm_kernel<<<dim3(64, 4), 256>>>(nullptr, W1, 256, 1);
    compute_e_kernel<<<4 * 512, 256>>>(a1, 4);
    attn_kernel<<<dim3(32, 4, 2), 256>>>();
    combine_kernel<<<dim3(32, 4), 256>>>(nullptr, 2, 256, 1, 1);

    // layer 2: D=256, H=1, msplit=8
    gemm_kernel<<<dim3(64, 1), 256>>>(nullptr, W2, 256, 1);
    compute_e_kernel<<<512, 256>>>(a2, 1);
    attn_kernel<<<dim3(32, 1, 8), 256>>>();
    combine_kernel<<<dim3(32, 1), 256>>>(out, 8, 64, 0, 0);
}

// round 5
// speedup vs baseline: 2.8999x; 1.9969x over previous
#include <cuda_runtime.h>
#include <cuda_fp16.h>
#include <math.h>

#define NROWS 4096
#define NW 128          // adjacency bitmask words per row
#define HID 64
#define ALPHA 0.2f
#define BRR 128         // attention rows per block
#define BM 32           // attention m-chunk
#define PSP 40          // ps pitch in halves (80 B)
#define HBP 72          // hsB pitch in halves (144 B)

// ---------------- device scratch ----------------
__device__ unsigned int g_adjbits[NROWS * NW];       // 2 MB packed adjacency
__device__ float g_h[4 * NROWS * HID];               // fp32 head features (for e)
__device__ __half g_h16[4 * NROWS * HID];            // fp16 head features (for mma)
__device__ float g_el[4 * NROWS];
__device__ float g_er[4 * NROWS];
__device__ unsigned int g_emax_u[4];                 // ordered-uint per-head max(e_r)
__device__ float g_buf[NROWS * 256];                 // inter-layer activations
__device__ float g_pnum[32 * 4 * 2 * BRR * HID];     // partial numerators
__device__ float g_pden[32 * 4 * 2 * BRR];           // partial denominators

// ---------------- helpers ----------------
__device__ __forceinline__ unsigned f2ord(float f) {
    unsigned u = __float_as_uint(f);
    return (u & 0x80000000u) ? ~u : (u | 0x80000000u);
}
__device__ __forceinline__ float ord2f(unsigned u) {
    return (u & 0x80000000u) ? __uint_as_float(u ^ 0x80000000u) : __uint_as_float(~u);
}
__device__ __forceinline__ void mma16816(float* c, unsigned a0, unsigned a1,
                                         unsigned a2, unsigned a3,
                                         unsigned b0, unsigned b1) {
    asm volatile(
        "mma.sync.aligned.m16n8k16.row.col.f32.f16.f16.f32 "
        "{%0,%1,%2,%3}, {%4,%5,%6,%7}, {%8,%9}, {%0,%1,%2,%3};"
        : "+f"(c[0]), "+f"(c[1]), "+f"(c[2]), "+f"(c[3])
        : "r"(a0), "r"(a1), "r"(a2), "r"(a3), "r"(b0), "r"(b1));
}

// ---------------- 1. pack adjacency into bitmask ----------------
__global__ void pack_adj_kernel(const int* __restrict__ adj) {
    int n = blockIdx.x;
    int warp = threadIdx.x >> 5, lane = threadIdx.x & 31;
    const int* row = adj + (size_t)n * NROWS;
    #pragma unroll 4
    for (int w = warp * 32; w < warp * 32 + 32; w++) {
        int v = row[w * 32 + lane];
        unsigned int bits = __ballot_sync(0xffffffffu, v > 0);
        if (lane == 0) g_adjbits[n * NW + w] = bits;
    }
}

// ---------------- 2. feature GEMM: g_h/g_h16 = X @ W[head] ----------------
__global__ __launch_bounds__(256) void gemm_kernel(const float* __restrict__ Xext,
                                                   const float* __restrict__ W,
                                                   int D, int useBuf) {
    if (blockIdx.x == 0 && blockIdx.y == 0 && threadIdx.x < 4) g_emax_u[threadIdx.x] = 0u;

    const float* __restrict__ X = useBuf ? (const float*)g_buf : Xext;
    const int head = blockIdx.y;
    const int r0 = blockIdx.x * 64;
    const int tid = threadIdx.x;
    __shared__ __align__(16) float Xs[64][33];
    __shared__ __align__(16) float Ws[32][64];
    float acc[4][4];
    #pragma unroll
    for (int r = 0; r < 4; r++)
        #pragma unroll
        for (int c = 0; c < 4; c++) acc[r][c] = 0.f;

    const int fr = tid >> 4, cg = tid & 15;
    const float* Wh = W + (size_t)head * D * HID;

    for (int d0 = 0; d0 < D; d0 += 32) {
        {
            int j = tid & 31, n0 = (tid >> 5) * 8;
            #pragma unroll
            for (int i = 0; i < 8; i++)
                Xs[n0 + i][j] = X[(size_t)(r0 + n0 + i) * D + d0 + j];
        }
        {
            int o = tid & 63, j0 = (tid >> 6) * 8;
            #pragma unroll
            for (int i = 0; i < 8; i++)
                Ws[j0 + i][o] = Wh[(size_t)(d0 + j0 + i) * HID + o];
        }
        __syncthreads();
        #pragma unroll
        for (int k = 0; k < 32; k++) {
            float4 wv = *(const float4*)&Ws[k][cg * 4];
            float x0 = Xs[fr * 4 + 0][k];
            float x1 = Xs[fr * 4 + 1][k];
            float x2 = Xs[fr * 4 + 2][k];
            float x3 = Xs[fr * 4 + 3][k];
            acc[0][0] += x0 * wv.x; acc[0][1] += x0 * wv.y; acc[0][2] += x0 * wv.z; acc[0][3] += x0 * wv.w;
            acc[1][0] += x1 * wv.x; acc[1][1] += x1 * wv.y; acc[1][2] += x1 * wv.z; acc[1][3] += x1 * wv.w;
            acc[2][0] += x2 * wv.x; acc[2][1] += x2 * wv.y; acc[2][2] += x2 * wv.z; acc[2][3] += x2 * wv.w;
            acc[3][0] += x3 * wv.x; acc[3][1] += x3 * wv.y; acc[3][2] += x3 * wv.z; acc[3][3] += x3 * wv.w;
        }
        __syncthreads();
    }
    float* hp = g_h + ((size_t)head * NROWS + r0) * HID;
    __half2* hp16 = (__half2*)(g_h16 + ((size_t)head * NROWS + r0) * HID);
    #pragma unroll
    for (int r = 0; r < 4; r++) {
        int rr = fr * 4 + r;
        *(float4*)&hp[(size_t)rr * HID + cg * 4] =
            make_float4(acc[r][0], acc[r][1], acc[r][2], acc[r][3]);
        hp16[rr * 32 + cg * 2]     = __floats2half2_rn(acc[r][0], acc[r][1]);
        hp16[rr * 32 + cg * 2 + 1] = __floats2half2_rn(acc[r][2], acc[r][3]);
    }
}

// ---------------- 3. e_l / e_r per (head, node), fused per-head max(e_r) ----------------
__global__ void compute_e_kernel(const float* __restrict__ a, int H) {
    int gw = (blockIdx.x * blockDim.x + threadIdx.x) >> 5;
    int lane = threadIdx.x & 31;
    int head = gw >> 12;
    int n = gw & (NROWS - 1);
    __shared__ float wmax[8];
    const float* hp = g_h + ((size_t)head * NROWS + n) * HID;
    const float* ah = a + head * 2 * HID;
    float sl = 0.f, sr = 0.f;
    #pragma unroll
    for (int i = lane; i < HID; i += 32) {
        float hv = hp[i];
        sl += hv * ah[i];
        sr += hv * ah[HID + i];
    }
    #pragma unroll
    for (int off = 16; off; off >>= 1) {
        sl += __shfl_xor_sync(0xffffffffu, sl, off);
        sr += __shfl_xor_sync(0xffffffffu, sr, off);
    }
    if (lane == 0) {
        g_el[head * NROWS + n] = sl;
        g_er[head * NROWS + n] = sr;
        wmax[threadIdx.x >> 5] = sr;
    }
    __syncthreads();
    if (threadIdx.x == 0) {
        float m = wmax[0];
        #pragma unroll
        for (int i = 1; i < 8; i++) m = fmaxf(m, wmax[i]);
        atomicMax(&g_emax_u[head], f2ord(m));
    }
}

// ---------------- 4. fused masked-softmax attention, fp16 tensor-core P@h ----------------
// 256 threads (8 warps). 128x64 tile. Warp w owns rows w*16..w*16+15.
__global__ __launch_bounds__(256, 2) void attn_kernel() {
    const int head = blockIdx.y;
    const int r0b = blockIdx.x * BRR;
    const int z = blockIdx.z;
    const int msplit = gridDim.z;
    const int mlen = NROWS / msplit;
    const int mstart = z * mlen;
    const int tid = threadIdx.x;
    const int lane = tid & 31, w = tid >> 5;

    __shared__ __align__(16) __half ps16[128 * PSP];   // P tile  (10.0 KB)
    __shared__ __align__(16) __half hsB[BM * HBP];     // h tile  (4.5 KB)
    __shared__ __align__(16) float ers[2048];          // e_r slice (8 KB max)
    __shared__ float dsum2[2][BRR];

    // stage e_r slice
    {
        const float4* er4 = (const float4*)(g_er + head * NROWS + mstart);
        float4* d4 = (float4*)ers;
        for (int i = tid; i < mlen / 4; i += 256) d4[i] = er4[i];
    }

    const int row = tid & 127;    // score-gen row
    const int sub = tid >> 7;     // score-gen k sub-range (16 each)
    const float el = g_el[head * NROWS + r0b + row];
    const float emax = ord2f(g_emax_u[head]);
    float M = el + emax;
    M = fmaxf(M, ALPHA * M);      // lrelu of an upper bound: exponents <= 0
    float dacc = 0.f;

    float acc[8][4];
    #pragma unroll
    for (int t = 0; t < 8; t++)
        #pragma unroll
        for (int c = 0; c < 4; c++) acc[t][c] = 0.f;

    const __half* hb16 = g_h16 + (size_t)head * NROWS * HID;
    const unsigned int* aw = g_adjbits + (size_t)(r0b + row) * NW;

    // precompute ldmatrix addresses (smem tiles reused in place)
    unsigned psaddr[2], hbaddr[2][4];
    {
        int grp = lane >> 3, li = lane & 7;
        int arow = w * 16 + li + (grp & 1) * 8;
        #pragma unroll
        for (int ks = 0; ks < 2; ks++) {
            int ak = ks * 16 + (grp >> 1) * 8;
            psaddr[ks] = (unsigned)__cvta_generic_to_shared(&ps16[arow * PSP + ak]);
            int bk = ks * 16 + (grp & 1) * 8 + li;
            #pragma unroll
            for (int np = 0; np < 4; np++) {
                int bn = np * 16 + (grp >> 1) * 8;
                hbaddr[ks][np] = (unsigned)__cvta_generic_to_shared(&hsB[bk * HBP + bn]);
            }
        }
    }
    const int srr = tid >> 3, sc8 = (tid & 7) * 8;   // h staging: 32 rows x 8 chunks
    uint4* hstg = (uint4*)&hsB[srr * HBP + sc8];
    uint4* pstg = (uint4*)&ps16[row * PSP + sub * 16];

    __syncthreads();   // ers ready

    for (int m0 = mstart; m0 < mstart + mlen; m0 += BM) {
        // stage h tile [32][64] fp16
        *hstg = *(const uint4*)&hb16[(size_t)(m0 + srr) * HID + sc8];
        // score-gen: 16 p for (row, sub), written as 2x STS.128 of fp16
        unsigned word = aw[m0 >> 5] >> (sub * 16);
        const float* erc = ers + (m0 - mstart) + sub * 16;
        unsigned hp[8];
        #pragma unroll
        for (int j4 = 0; j4 < 4; j4++) {
            float4 e4 = *(const float4*)&erc[j4 * 4];
            float ev[4] = {e4.x, e4.y, e4.z, e4.w};
            float pv[4];
            #pragma unroll
            for (int t = 0; t < 4; t++) {
                float s = el + ev[t];
                s = fmaxf(s, ALPHA * s);
                pv[t] = ((word >> (j4 * 4 + t)) & 1u) ? __expf(s - M) : 0.f;
            }
            __half2 h0 = __floats2half2_rn(pv[0], pv[1]);
            __half2 h1 = __floats2half2_rn(pv[2], pv[3]);
            float2 f0 = __half22float2(h0), f1 = __half22float2(h1);
            dacc += (f0.x + f0.y) + (f1.x + f1.y);   // den consistent with fp16 num
            hp[j4 * 2]     = *(unsigned*)&h0;
            hp[j4 * 2 + 1] = *(unsigned*)&h1;
        }
        pstg[0] = make_uint4(hp[0], hp[1], hp[2], hp[3]);
        pstg[1] = make_uint4(hp[4], hp[5], hp[6], hp[7]);
        __syncthreads();

        // tensor-core P @ h: per warp 2 A-ldmatrix + 8 B-ldmatrix + 16 HMMA
        #pragma unroll
        for (int ks = 0; ks < 2; ks++) {
            unsigned a0, a1, a2, a3;
            asm volatile("ldmatrix.sync.aligned.m8n8.x4.shared.b16 {%0,%1,%2,%3}, [%4];"
                         : "=r"(a0), "=r"(a1), "=r"(a2), "=r"(a3) : "r"(psaddr[ks]));
            #pragma unroll
            for (int np = 0; np < 4; np++) {
                unsigned b0, b1, b2, b3;
                asm volatile("ldmatrix.sync.aligned.m8n8.x4.trans.shared.b16 {%0,%1,%2,%3}, [%4];"
                             : "=r"(b0), "=r"(b1), "=r"(b2), "=r"(b3) : "r"(hbaddr[ks][np]));
                mma16816(acc[np * 2],     a0, a1, a2, a3, b0, b1);
                mma16816(acc[np * 2 + 1], a0, a1, a2, a3, b2, b3);
            }
        }
        __syncthreads();
    }

    dsum2[sub][row] = dacc;
    __syncthreads();

    const int pidx = (blockIdx.x * gridDim.y + head) * msplit + z;
    if (tid < BRR) g_pden[(size_t)pidx * BRR + tid] = dsum2[0][tid] + dsum2[1][tid];

    float* np_ = g_pnum + (size_t)pidx * (BRR * HID);
    const int crow = w * 16 + (lane >> 2);
    const int ccol = (lane & 3) * 2;
    #pragma unroll
    for (int nt = 0; nt < 8; nt++) {
        *(float2*)&np_[(size_t)crow * HID + nt * 8 + ccol]       = make_float2(acc[nt][0], acc[nt][1]);
        *(float2*)&np_[(size_t)(crow + 8) * HID + nt * 8 + ccol] = make_float2(acc[nt][2], acc[nt][3]);
    }
}

// ---------------- 5. combine partials -> dest (divide + optional ELU) ----------------
__global__ void combine_kernel(float* __restrict__ dest, int msplit,
                               int ostride, int doElu, int useBuf) {
    const int rb = blockIdx.x, head = blockIdx.y, H = gridDim.y;
    float* obase = useBuf ? g_buf : dest;
    const int base = (rb * H + head) * msplit;
    for (int idx = threadIdx.x; idx < BRR * HID; idx += 256) {
        int row = idx >> 6;
        float num = 0.f, den = 0.f;
        for (int zz = 0; zz < msplit; zz++) {
            num += g_pnum[(size_t)(base + zz) * (BRR * HID) + idx];
            den += g_pden[(size_t)(base + zz) * BRR + row];
        }
        float t = num / den;
        if (doElu) t = (t > 0.f) ? t : expm1f(t);
        obase[(size_t)(rb * BRR + row) * ostride + head * HID + (idx & 63)] = t;
    }
}

// ---------------- launch ----------------
extern "C" void kernel_launch(void* const* d_in, const int* in_sizes, int n_in,
                              void* d_out, int out_size) {
    const float* x   = (const float*)d_in[0];
    const int*   adj = (const int*)d_in[1];
    const float* W0  = (const float*)d_in[2];
    const float* a0  = (const float*)d_in[3];
    const float* W1  = (const float*)d_in[4];
    const float* a1  = (const float*)d_in[5];
    const float* W2  = (const float*)d_in[6];
    const float* a2  = (const float*)d_in[7];
    float* out = (float*)d_out;

    pack_adj_kernel<<<NROWS, 128>>>(adj);

    // layer 0: D=128, H=4, msplit=2
    gemm_kernel<<<dim3(64, 4), 256>>>(x, W0, 128, 0);
    compute_e_kernel<<<4 * 512, 256>>>(a0, 4);
    attn_kernel<<<dim3(32, 4, 2), 256>>>();
    combine_kernel<<<dim3(32, 4), 256>>>(nullptr, 2, 256, 1, 1);

    // layer 1: D=256, H=4, msplit=2
    gemm_kernel<<<dim3(64, 4), 256>>>(nullptr, W1, 256, 1);
    compute_e_kernel<<<4 * 512, 256>>>(a1, 4);
    attn_kernel<<<dim3(32, 4, 2), 256>>>();
    combine_kernel<<<dim3(32, 4), 256>>>(nullptr, 2, 256, 1, 1);

    // layer 2: D=256, H=1, msplit=8
    gemm_kernel<<<dim3(64, 1), 256>>>(nullptr, W2, 256, 1);
    compute_e_kernel<<<512, 256>>>(a2, 1);
    attn_kernel<<<dim3(32, 1, 8), 256>>>();
    combine_kernel<<<dim3(32, 1), 256>>>(out, 8, 64, 0, 0);
}

// round 6
// speedup vs baseline: 4.1895x; 1.4447x over previous
#include <cuda_runtime.h>
#include <cuda_fp16.h>
#include <math.h>

#define NROWS 4096
#define NW 128          // adjacency bitmask words per row
#define HID 64
#define ALPHA 0.2f
#define BRR 128         // attention rows per block
#define BM 64           // attention m-chunk
#define PSP 72          // ps pitch in halves (144 B)
#define HBP 72          // hsB pitch in halves (144 B)

// ---------------- device scratch ----------------
__device__ unsigned int g_adjbits[NROWS * NW];       // 2 MB packed adjacency
__device__ float g_h[4 * NROWS * HID];               // fp32 head features (for e)
__device__ __half g_h16[4 * NROWS * HID];            // fp16 head features (for mma)
__device__ float g_el[4 * NROWS];
__device__ float g_er[4 * NROWS];
__device__ unsigned int g_emax_u[4];                 // ordered-uint per-head max(e_r)
__device__ float g_buf[NROWS * 256];                 // inter-layer activations
__device__ float g_pnum[32 * 4 * 2 * BRR * HID];     // partial numerators
__device__ float g_pden[32 * 4 * 2 * BRR];           // partial denominators

// ---------------- helpers ----------------
__device__ __forceinline__ unsigned f2ord(float f) {
    unsigned u = __float_as_uint(f);
    return (u & 0x80000000u) ? ~u : (u | 0x80000000u);
}
__device__ __forceinline__ float ord2f(unsigned u) {
    return (u & 0x80000000u) ? __uint_as_float(u ^ 0x80000000u) : __uint_as_float(~u);
}
__device__ __forceinline__ unsigned long long packAC(float a, float c) {
    unsigned long long r;
    asm("mov.b64 %0, {%1, %2};" : "=l"(r) : "f"(a), "f"(c));
    return r;
}
__device__ __forceinline__ float2 mul2(unsigned long long a, unsigned long long b) {
    unsigned long long r;
    asm("mul.rn.f32x2 %0, %1, %2;" : "=l"(r) : "l"(a), "l"(b));
    float2 f;
    asm("mov.b64 {%0, %1}, %2;" : "=f"(f.x), "=f"(f.y) : "l"(r));
    return f;
}
__device__ __forceinline__ void mma16816(float* c, unsigned a0, unsigned a1,
                                         unsigned a2, unsigned a3,
                                         unsigned b0, unsigned b1) {
    asm volatile(
        "mma.sync.aligned.m16n8k16.row.col.f32.f16.f16.f32 "
        "{%0,%1,%2,%3}, {%4,%5,%6,%7}, {%8,%9}, {%0,%1,%2,%3};"
        : "+f"(c[0]), "+f"(c[1]), "+f"(c[2]), "+f"(c[3])
        : "r"(a0), "r"(a1), "r"(a2), "r"(a3), "r"(b0), "r"(b1));
}

// ---------------- 1. pack adjacency into bitmask ----------------
__global__ void pack_adj_kernel(const int* __restrict__ adj) {
    int n = blockIdx.x;
    int warp = threadIdx.x >> 5, lane = threadIdx.x & 31;
    const int* row = adj + (size_t)n * NROWS;
    #pragma unroll 4
    for (int w = warp * 32; w < warp * 32 + 32; w++) {
        int v = row[w * 32 + lane];
        unsigned int bits = __ballot_sync(0xffffffffu, v > 0);
        if (lane == 0) g_adjbits[n * NW + w] = bits;
    }
}

// ---------------- 2. feature GEMM: g_h/g_h16 = X @ W[head] ----------------
__global__ __launch_bounds__(256) void gemm_kernel(const float* __restrict__ Xext,
                                                   const float* __restrict__ W,
                                                   int D, int useBuf) {
    if (blockIdx.x == 0 && blockIdx.y == 0 && threadIdx.x < 4) g_emax_u[threadIdx.x] = 0u;

    const float* __restrict__ X = useBuf ? (const float*)g_buf : Xext;
    const int head = blockIdx.y;
    const int r0 = blockIdx.x * 64;
    const int tid = threadIdx.x;
    __shared__ __align__(16) float Xs[64][33];
    __shared__ __align__(16) float Ws[32][64];
    float acc[4][4];
    #pragma unroll
    for (int r = 0; r < 4; r++)
        #pragma unroll
        for (int c = 0; c < 4; c++) acc[r][c] = 0.f;

    const int fr = tid >> 4, cg = tid & 15;
    const float* Wh = W + (size_t)head * D * HID;

    for (int d0 = 0; d0 < D; d0 += 32) {
        {
            int j = tid & 31, n0 = (tid >> 5) * 8;
            #pragma unroll
            for (int i = 0; i < 8; i++)
                Xs[n0 + i][j] = X[(size_t)(r0 + n0 + i) * D + d0 + j];
        }
        {
            int o = tid & 63, j0 = (tid >> 6) * 8;
            #pragma unroll
            for (int i = 0; i < 8; i++)
                Ws[j0 + i][o] = Wh[(size_t)(d0 + j0 + i) * HID + o];
        }
        __syncthreads();
        #pragma unroll
        for (int k = 0; k < 32; k++) {
            float4 wv = *(const float4*)&Ws[k][cg * 4];
            float x0 = Xs[fr * 4 + 0][k];
            float x1 = Xs[fr * 4 + 1][k];
            float x2 = Xs[fr * 4 + 2][k];
            float x3 = Xs[fr * 4 + 3][k];
            acc[0][0] += x0 * wv.x; acc[0][1] += x0 * wv.y; acc[0][2] += x0 * wv.z; acc[0][3] += x0 * wv.w;
            acc[1][0] += x1 * wv.x; acc[1][1] += x1 * wv.y; acc[1][2] += x1 * wv.z; acc[1][3] += x1 * wv.w;
            acc[2][0] += x2 * wv.x; acc[2][1] += x2 * wv.y; acc[2][2] += x2 * wv.z; acc[2][3] += x2 * wv.w;
            acc[3][0] += x3 * wv.x; acc[3][1] += x3 * wv.y; acc[3][2] += x3 * wv.z; acc[3][3] += x3 * wv.w;
        }
        __syncthreads();
    }
    float* hp = g_h + ((size_t)head * NROWS + r0) * HID;
    __half2* hp16 = (__half2*)(g_h16 + ((size_t)head * NROWS + r0) * HID);
    #pragma unroll
    for (int r = 0; r < 4; r++) {
        int rr = fr * 4 + r;
        *(float4*)&hp[(size_t)rr * HID + cg * 4] =
            make_float4(acc[r][0], acc[r][1], acc[r][2], acc[r][3]);
        hp16[rr * 32 + cg * 2]     = __floats2half2_rn(acc[r][0], acc[r][1]);
        hp16[rr * 32 + cg * 2 + 1] = __floats2half2_rn(acc[r][2], acc[r][3]);
    }
}

// ---------------- 3. e_l / e_r per (head, node), fused per-head max(e_r) ----------------
__global__ void compute_e_kernel(const float* __restrict__ a, int H) {
    int gw = (blockIdx.x * blockDim.x + threadIdx.x) >> 5;
    int lane = threadIdx.x & 31;
    int head = gw >> 12;
    int n = gw & (NROWS - 1);
    __shared__ float wmax[8];
    const float* hp = g_h + ((size_t)head * NROWS + n) * HID;
    const float* ah = a + head * 2 * HID;
    float sl = 0.f, sr = 0.f;
    #pragma unroll
    for (int i = lane; i < HID; i += 32) {
        float hv = hp[i];
        sl += hv * ah[i];
        sr += hv * ah[HID + i];
    }
    #pragma unroll
    for (int off = 16; off; off >>= 1) {
        sl += __shfl_xor_sync(0xffffffffu, sl, off);
        sr += __shfl_xor_sync(0xffffffffu, sr, off);
    }
    if (lane == 0) {
        g_el[head * NROWS + n] = sl;
        g_er[head * NROWS + n] = sr;
        wmax[threadIdx.x >> 5] = sr;
    }
    __syncthreads();
    if (threadIdx.x == 0) {
        float m = wmax[0];
        #pragma unroll
        for (int i = 1; i < 8; i++) m = fmaxf(m, wmax[i]);
        atomicMax(&g_emax_u[head], f2ord(m));
    }
}

// ---------------- 4. fused masked-softmax attention, expless score-gen + fp16 MMA ----------------
// 256 threads (8 warps). 128x64 tile, BM=64 m-chunks. Warp w owns rows w*16..w*16+15.
__global__ __launch_bounds__(256, 2) void attn_kernel() {
    const int head = blockIdx.y;
    const int r0b = blockIdx.x * BRR;
    const int z = blockIdx.z;
    const int msplit = gridDim.z;
    const int mlen = NROWS / msplit;
    const int mstart = z * mlen;
    const int tid = threadIdx.x;
    const int lane = tid & 31, w = tid >> 5;

    __shared__ __align__(16) __half ps16[128 * PSP];   // P tile (18.4 KB)
    __shared__ __align__(16) __half hsB[BM * HBP];     // h tile (9.2 KB)
    __shared__ __align__(16) float2 bd[2048];          // per-column (B, D) (16 KB max)
    __shared__ float dsum2[2][BRR];

    const int row = tid & 127;    // score-gen row
    const int sub = tid >> 7;     // score-gen k sub-range (32 each)
    const float el = g_el[head * NROWS + r0b + row];
    const float emax = ord2f(g_emax_u[head]);
    const float s0 = el + emax;
    const float M = fmaxf(s0, ALPHA * s0);
    const unsigned long long AC = packAC(__expf(s0 - M), __expf(ALPHA * s0 - M));
    float dacc = 0.f;

    // precompute per-column (B, D) = (exp(er-emax), exp(0.2*(er-emax)))
    for (int i = tid; i < mlen; i += 256) {
        float t = g_er[head * NROWS + mstart + i] - emax;
        bd[i] = make_float2(__expf(t), __expf(ALPHA * t));
    }

    float acc[8][4];
    #pragma unroll
    for (int t = 0; t < 8; t++)
        #pragma unroll
        for (int c = 0; c < 4; c++) acc[t][c] = 0.f;

    const __half* hb16 = g_h16 + (size_t)head * NROWS * HID;
    const unsigned int* aw = g_adjbits + (size_t)(r0b + row) * NW;

    // ldmatrix bases
    unsigned psbase, hbbase;
    {
        int grp = lane >> 3, li = lane & 7;
        int arow = w * 16 + li + (grp & 1) * 8;
        psbase = (unsigned)__cvta_generic_to_shared(&ps16[arow * PSP + (grp >> 1) * 8]);
        hbbase = (unsigned)__cvta_generic_to_shared(&hsB[((grp & 1) * 8 + li) * HBP + (grp >> 1) * 8]);
    }
    const int srr = tid >> 3, sc8 = (tid & 7) * 8;   // h staging: rows, 8-half chunks
    uint4* hstg0 = (uint4*)&hsB[srr * HBP + sc8];
    uint4* hstg1 = (uint4*)&hsB[(srr + 32) * HBP + sc8];
    uint4* pstg = (uint4*)&ps16[row * PSP + sub * 32];

    __syncthreads();   // bd ready

    for (int m0 = mstart; m0 < mstart + mlen; m0 += BM) {
        // stage h tile [64][64] fp16
        *hstg0 = *(const uint4*)&hb16[(size_t)(m0 + srr) * HID + sc8];
        *hstg1 = *(const uint4*)&hb16[(size_t)(m0 + 32 + srr) * HID + sc8];
        // score-gen: 32 p for (row, sub): p = mask * max(A*B, C*D)
        unsigned word = aw[(m0 >> 5) + sub];
        const float2* bdc = bd + (m0 - mstart) + sub * 32;
        #pragma unroll
        for (int g8 = 0; g8 < 4; g8++) {
            unsigned hh[4];
            #pragma unroll
            for (int g2 = 0; g2 < 2; g2++) {
                float4 q0 = *(const float4*)&bdc[g8 * 8 + g2 * 4];      // (B,D)x2
                float4 q1 = *(const float4*)&bdc[g8 * 8 + g2 * 4 + 2];
                float2 u0 = mul2(AC, *(const unsigned long long*)&q0.x);
                float2 u1 = mul2(AC, *(const unsigned long long*)&q0.z);
                float2 u2 = mul2(AC, *(const unsigned long long*)&q1.x);
                float2 u3 = mul2(AC, *(const unsigned long long*)&q1.z);
                int jb = g8 * 8 + g2 * 4;
                float p0 = ((word >> (jb + 0)) & 1u) ? fmaxf(u0.x, u0.y) : 0.f;
                float p1 = ((word >> (jb + 1)) & 1u) ? fmaxf(u1.x, u1.y) : 0.f;
                float p2 = ((word >> (jb + 2)) & 1u) ? fmaxf(u2.x, u2.y) : 0.f;
                float p3 = ((word >> (jb + 3)) & 1u) ? fmaxf(u3.x, u3.y) : 0.f;
                dacc += (p0 + p1) + (p2 + p3);
                __half2 h0 = __floats2half2_rn(p0, p1);
                __half2 h1 = __floats2half2_rn(p2, p3);
                hh[g2 * 2]     = *(unsigned*)&h0;
                hh[g2 * 2 + 1] = *(unsigned*)&h1;
            }
            pstg[g8] = make_uint4(hh[0], hh[1], hh[2], hh[3]);
        }
        __syncthreads();

        // tensor-core P @ h: per warp 4 A-ldmatrix + 16 B-ldmatrix + 32 HMMA
        #pragma unroll
        for (int ks = 0; ks < 4; ks++) {
            unsigned a0, a1, a2, a3;
            asm volatile("ldmatrix.sync.aligned.m8n8.x4.shared.b16 {%0,%1,%2,%3}, [%4];"
                         : "=r"(a0), "=r"(a1), "=r"(a2), "=r"(a3)
                         : "r"(psbase + ks * 32));
            #pragma unroll
            for (int np = 0; np < 4; np++) {
                unsigned b0, b1, b2, b3;
                asm volatile("ldmatrix.sync.aligned.m8n8.x4.trans.shared.b16 {%0,%1,%2,%3}, [%4];"
                             : "=r"(b0), "=r"(b1), "=r"(b2), "=r"(b3)
                             : "r"(hbbase + ks * (16 * HBP * 2) + np * 32));
                mma16816(acc[np * 2],     a0, a1, a2, a3, b0, b1);
                mma16816(acc[np * 2 + 1], a0, a1, a2, a3, b2, b3);
            }
        }
        __syncthreads();
    }

    dsum2[sub][row] = dacc;
    __syncthreads();

    const int pidx = (blockIdx.x * gridDim.y + head) * msplit + z;
    if (tid < BRR) g_pden[(size_t)pidx * BRR + tid] = dsum2[0][tid] + dsum2[1][tid];

    float* np_ = g_pnum + (size_t)pidx * (BRR * HID);
    const int crow = w * 16 + (lane >> 2);
    const int ccol = (lane & 3) * 2;
    #pragma unroll
    for (int nt = 0; nt < 8; nt++) {
        *(float2*)&np_[(size_t)crow * HID + nt * 8 + ccol]       = make_float2(acc[nt][0], acc[nt][1]);
        *(float2*)&np_[(size_t)(crow + 8) * HID + nt * 8 + ccol] = make_float2(acc[nt][2], acc[nt][3]);
    }
}

// ---------------- 5. combine partials -> dest (divide + optional ELU) ----------------
__global__ void combine_kernel(float* __restrict__ dest, int msplit,
                               int ostride, int doElu, int useBuf) {
    const int rb = blockIdx.x, head = blockIdx.y, H = gridDim.y;
    float* obase = useBuf ? g_buf : dest;
    const int base = (rb * H + head) * msplit;
    for (int idx = threadIdx.x; idx < BRR * HID; idx += 256) {
        int row = idx >> 6;
        float num = 0.f, den = 0.f;
        for (int zz = 0; zz < msplit; zz++) {
            num += g_pnum[(size_t)(base + zz) * (BRR * HID) + idx];
            den += g_pden[(size_t)(base + zz) * BRR + row];
        }
        float t = num / den;
        if (doElu) t = (t > 0.f) ? t : expm1f(t);
        obase[(size_t)(rb * BRR + row) * ostride + head * HID + (idx & 63)] = t;
    }
}

// ---------------- launch ----------------
extern "C" void kernel_launch(void* const* d_in, const int* in_sizes, int n_in,
                              void* d_out, int out_size) {
    const float* x   = (const float*)d_in[0];
    const int*   adj = (const int*)d_in[1];
    const float* W0  = (const float*)d_in[2];
    const float* a0  = (const float*)d_in[3];
    const float* W1  = (const float*)d_in[4];
    const float* a1  = (const float*)d_in[5];
    const float* W2  = (const float*)d_in[6];
    const float* a2  = (const float*)d_in[7];
    float* out = (float*)d_out;

    pack_adj_kernel<<<NROWS, 128>>>(adj);

    // layer 0: D=128, H=4, msplit=2
    gemm_kernel<<<dim3(64, 4), 256>>>(x, W0, 128, 0);
    compute_e_kernel<<<4 * 512, 256>>>(a0, 4);
    attn_kernel<<<dim3(32, 4, 2), 256>>>();
    combine_kernel<<<dim3(32, 4), 256>>>(nullptr, 2, 256, 1, 1);

    // layer 1: D=256, H=4, msplit=2
    gemm_kernel<<<dim3(64, 4), 256>>>(nullptr, W1, 256, 1);
    compute_e_kernel<<<4 * 512, 256>>>(a1, 4);
    attn_kernel<<<dim3(32, 4, 2), 256>>>();
    combine_kernel<<<dim3(32, 4), 256>>>(nullptr, 2, 256, 1, 1);

    // layer 2: D=256, H=1, msplit=8
    gemm_kernel<<<dim3(64, 1), 256>>>(nullptr, W2, 256, 1);
    compute_e_kernel<<<512, 256>>>(a2, 1);
    attn_kernel<<<dim3(32, 1, 8), 256>>>();
    combine_kernel<<<dim3(32, 1), 256>>>(out, 8, 64, 0, 0);
}

// round 9
// speedup vs baseline: 4.5492x; 1.0859x over previous
#include <cuda_runtime.h>
#include <cuda_fp16.h>
#include <math.h>

#define NROWS 4096
#define NW 128          // adjacency bitmask words per row
#define HID 64
#define ALPHA 0.2f
#define BRR 128         // attention rows per block
#define BM 64           // attention m-chunk
#define HBP 72          // h tile pitch in halves (144 B)

// ---------------- device scratch ----------------
__device__ unsigned int g_adjbits[NROWS * NW];       // 2 MB packed adjacency
__device__ float g_h[4 * NROWS * HID];               // fp32 head features (for e)
__device__ __half g_h16[4 * NROWS * HID];            // fp16 head features (for mma B)
__device__ float g_el[4 * NROWS];
__device__ float g_er[4 * NROWS];
__device__ unsigned int g_emax_u[4];                 // ordered-uint per-head max(e_r)
__device__ float g_buf[NROWS * 256];                 // inter-layer activations
__device__ float g_pnum[32 * 4 * 2 * BRR * HID];     // partial numerators
__device__ float g_pden[32 * 4 * 2 * BRR];           // partial denominators

// ---------------- helpers ----------------
__device__ __forceinline__ unsigned f2ord(float f) {
    unsigned u = __float_as_uint(f);
    return (u & 0x80000000u) ? ~u : (u | 0x80000000u);
}
__device__ __forceinline__ float ord2f(unsigned u) {
    return (u & 0x80000000u) ? __uint_as_float(u ^ 0x80000000u) : __uint_as_float(~u);
}
__device__ __forceinline__ unsigned long long packAC(float a, float c) {
    unsigned long long r;
    asm("mov.b64 %0, {%1, %2};" : "=l"(r) : "f"(a), "f"(c));
    return r;
}
__device__ __forceinline__ float2 mul2(unsigned long long a, unsigned long long b) {
    unsigned long long r;
    asm("mul.rn.f32x2 %0, %1, %2;" : "=l"(r) : "l"(a), "l"(b));
    float2 f;
    asm("mov.b64 {%0, %1}, %2;" : "=f"(f.x), "=f"(f.y) : "l"(r));
    return f;
}
__device__ __forceinline__ void mma16816(float* c, unsigned a0, unsigned a1,
                                         unsigned a2, unsigned a3,
                                         unsigned b0, unsigned b1) {
    asm volatile(
        "mma.sync.aligned.m16n8k16.row.col.f32.f16.f16.f32 "
        "{%0,%1,%2,%3}, {%4,%5,%6,%7}, {%8,%9}, {%0,%1,%2,%3};"
        : "+f"(c[0]), "+f"(c[1]), "+f"(c[2]), "+f"(c[3])
        : "r"(a0), "r"(a1), "r"(a2), "r"(a3), "r"(b0), "r"(b1));
}

// ---------------- 1. pack adjacency into bitmask ----------------
__global__ void pack_adj_kernel(const int* __restrict__ adj) {
    int n = blockIdx.x;
    int warp = threadIdx.x >> 5, lane = threadIdx.x & 31;
    const int* row = adj + (size_t)n * NROWS;
    #pragma unroll 4
    for (int w = warp * 32; w < warp * 32 + 32; w++) {
        int v = row[w * 32 + lane];
        unsigned int bits = __ballot_sync(0xffffffffu, v > 0);
        if (lane == 0) g_adjbits[n * NW + w] = bits;
    }
}

// ---------------- 2. feature GEMM: g_h (fp32) + g_h16 (fp16) = X @ W[head] ----------------
__global__ __launch_bounds__(256) void gemm_kernel(const float* __restrict__ Xext,
                                                   const float* __restrict__ W,
                                                   int D, int useBuf) {
    if (blockIdx.x == 0 && blockIdx.y == 0 && threadIdx.x < 4) g_emax_u[threadIdx.x] = 0u;

    const float* __restrict__ X = useBuf ? (const float*)g_buf : Xext;
    const int head = blockIdx.y;
    const int r0 = blockIdx.x * 64;
    const int tid = threadIdx.x;
    __shared__ __align__(16) float Xs[64][33];
    __shared__ __align__(16) float Ws[32][64];
    float acc[4][4];
    #pragma unroll
    for (int r = 0; r < 4; r++)
        #pragma unroll
        for (int c = 0; c < 4; c++) acc[r][c] = 0.f;

    const int fr = tid >> 4, cg = tid & 15;
    const float* Wh = W + (size_t)head * D * HID;

    for (int d0 = 0; d0 < D; d0 += 32) {
        {
            int j = tid & 31, n0 = (tid >> 5) * 8;
            #pragma unroll
            for (int i = 0; i < 8; i++)
                Xs[n0 + i][j] = X[(size_t)(r0 + n0 + i) * D + d0 + j];
        }
        {
            int o = tid & 63, j0 = (tid >> 6) * 8;
            #pragma unroll
            for (int i = 0; i < 8; i++)
                Ws[j0 + i][o] = Wh[(size_t)(d0 + j0 + i) * HID + o];
        }
        __syncthreads();
        #pragma unroll
        for (int k = 0; k < 32; k++) {
            float4 wv = *(const float4*)&Ws[k][cg * 4];
            float x0 = Xs[fr * 4 + 0][k];
            float x1 = Xs[fr * 4 + 1][k];
            float x2 = Xs[fr * 4 + 2][k];
            float x3 = Xs[fr * 4 + 3][k];
            acc[0][0] += x0 * wv.x; acc[0][1] += x0 * wv.y; acc[0][2] += x0 * wv.z; acc[0][3] += x0 * wv.w;
            acc[1][0] += x1 * wv.x; acc[1][1] += x1 * wv.y; acc[1][2] += x1 * wv.z; acc[1][3] += x1 * wv.w;
            acc[2][0] += x2 * wv.x; acc[2][1] += x2 * wv.y; acc[2][2] += x2 * wv.z; acc[2][3] += x2 * wv.w;
            acc[3][0] += x3 * wv.x; acc[3][1] += x3 * wv.y; acc[3][2] += x3 * wv.z; acc[3][3] += x3 * wv.w;
        }
        __syncthreads();
    }
    float* hp = g_h + ((size_t)head * NROWS + r0) * HID;
    __half2* hp16 = (__half2*)(g_h16 + ((size_t)head * NROWS + r0) * HID);
    #pragma unroll
    for (int r = 0; r < 4; r++) {
        int rr = fr * 4 + r;
        *(float4*)&hp[(size_t)rr * HID + cg * 4] =
            make_float4(acc[r][0], acc[r][1], acc[r][2], acc[r][3]);
        hp16[rr * 32 + cg * 2]     = __floats2half2_rn(acc[r][0], acc[r][1]);
        hp16[rr * 32 + cg * 2 + 1] = __floats2half2_rn(acc[r][2], acc[r][3]);
    }
}

// ---------------- 3. e_l / e_r per (head, node), fused per-head max(e_r) ----------------
__global__ void compute_e_kernel(const float* __restrict__ a, int H) {
    int gw = (blockIdx.x * blockDim.x + threadIdx.x) >> 5;
    int lane = threadIdx.x & 31;
    int head = gw >> 12;
    int n = gw & (NROWS - 1);
    __shared__ float wmax[8];
    const float* hp = g_h + ((size_t)head * NROWS + n) * HID;
    const float* ah = a + head * 2 * HID;
    float sl = 0.f, sr = 0.f;
    #pragma unroll
    for (int i = lane; i < HID; i += 32) {
        float hv = hp[i];
        sl += hv * ah[i];
        sr += hv * ah[HID + i];
    }
    #pragma unroll
    for (int off = 16; off; off >>= 1) {
        sl += __shfl_xor_sync(0xffffffffu, sl, off);
        sr += __shfl_xor_sync(0xffffffffu, sr, off);
    }
    if (lane == 0) {
        g_el[head * NROWS + n] = sl;
        g_er[head * NROWS + n] = sr;
        wmax[threadIdx.x >> 5] = sr;
    }
    __syncthreads();
    if (threadIdx.x == 0) {
        float m = wmax[0];
        #pragma unroll
        for (int i = 1; i < 8; i++) m = fmaxf(m, wmax[i]);
        atomicMax(&g_emax_u[head], f2ord(m));
    }
}

// ---------------- 4. fused attention: in-register A frags + mma.sync ----------------
// 128 threads (4 warps). 128x64 tile; warp w owns rows w*32..w*32+31.
__global__ __launch_bounds__(128, 3) void attn_kernel() {
    const int head = blockIdx.y;
    const int r0b = blockIdx.x * BRR;
    const int z = blockIdx.z;
    const int msplit = gridDim.z;
    const int mlen = NROWS / msplit;
    const int mstart = z * mlen;
    const int tid = threadIdx.x;
    const int lane = tid & 31, w = tid >> 5;

    __shared__ __align__(16) __half hsB[2][BM * HBP];  // double-buffered h tile (18.4 KB)
    __shared__ __align__(16) float2 bd[2048];          // per-column (B, D) (16 KB max)

    // per-column (B, D) = (exp(er-emax), exp(alpha*(er-emax)))
    const float emax = ord2f(g_emax_u[head]);
    for (int i = tid; i < mlen; i += 128) {
        float t = g_er[head * NROWS + mstart + i] - emax;
        bd[i] = make_float2(__expf(t), __expf(ALPHA * t));
    }

    // 4 owned score rows: w*32 + (lane>>2) + {0,8,16,24}
    const int rq = lane >> 2;
    const int c2 = (lane & 3) * 2;
    unsigned long long AC[4];
    float dacc[4];
    const unsigned* awp[4];
    #pragma unroll
    for (int i = 0; i < 4; i++) {
        int rowi = w * 32 + rq + i * 8;
        float el = g_el[head * NROWS + r0b + rowi];
        float s0 = el + emax;
        float M = fmaxf(s0, ALPHA * s0);       // per-row shift (num & den consistent)
        AC[i] = packAC(__expf(s0 - M), __expf(ALPHA * s0 - M));
        dacc[i] = 0.f;
        awp[i] = g_adjbits + (size_t)(r0b + rowi) * NW;
    }

    float acc[2][8][4];
    #pragma unroll
    for (int hh = 0; hh < 2; hh++)
        #pragma unroll
        for (int nt = 0; nt < 8; nt++)
            #pragma unroll
            for (int c = 0; c < 4; c++) acc[hh][nt][c] = 0.f;

    const __half* hb16 = g_h16 + (size_t)head * NROWS * HID;

    // B ldmatrix base (same mapping as the verified R5 kernel)
    const int grp = lane >> 3, li = lane & 7;
    const unsigned hbS = (unsigned)__cvta_generic_to_shared(
        &hsB[0][((grp & 1) * 8 + li) * HBP + (grp >> 1) * 8]);
    const unsigned bufstride = BM * HBP * 2;   // bytes between buffers

    // h staging: 4x 16B per thread
    int srow[4], sc8[4];
    #pragma unroll
    for (int i = 0; i < 4; i++) {
        int idx = tid + i * 128;
        srow[i] = idx >> 3;
        sc8[i] = (idx & 7) * 8;
    }

    __syncthreads();   // bd ready

    int bsel = 0;
    for (int m0 = mstart; m0 < mstart + mlen; m0 += BM, bsel ^= 1) {
        // stage h tile [64][64] into buffer bsel
        #pragma unroll
        for (int i = 0; i < 4; i++)
            *(uint4*)&hsB[bsel][srow[i] * HBP + sc8[i]] =
                *(const uint4*)&hb16[(size_t)(m0 + srow[i]) * HID + sc8[i]];
        // adjacency words for my 4 rows (2 words = 64 bits each)
        uint2 aj[4];
        #pragma unroll
        for (int i = 0; i < 4; i++) aj[i] = *(const uint2*)(awp[i] + (m0 >> 5));
        __syncthreads();

        const float4* bd4 = (const float4*)(bd + (m0 - mstart));
        #pragma unroll
        for (int ks = 0; ks < 4; ks++) {
            float4 q0 = bd4[ks * 8 + (lane & 3)];        // (B,D) for k=c2, c2+1
            float4 q1 = bd4[ks * 8 + 4 + (lane & 3)];    // (B,D) for k=c2+8, c2+9
            unsigned afr[8];
            #pragma unroll
            for (int i = 0; i < 4; i++) {
                unsigned wrd = (ks < 2) ? aj[i].x : aj[i].y;
                int sh = (ks & 1) * 16 + c2;
                float2 u0 = mul2(AC[i], *(const unsigned long long*)&q0.x);
                float2 u1 = mul2(AC[i], *(const unsigned long long*)&q0.z);
                float2 u2 = mul2(AC[i], *(const unsigned long long*)&q1.x);
                float2 u3 = mul2(AC[i], *(const unsigned long long*)&q1.z);
                float p0 = ((wrd >> sh) & 1u)       ? fmaxf(u0.x, u0.y) : 0.f;
                float p1 = ((wrd >> (sh + 1)) & 1u) ? fmaxf(u1.x, u1.y) : 0.f;
                float p2 = ((wrd >> (sh + 8)) & 1u) ? fmaxf(u2.x, u2.y) : 0.f;
                float p3 = ((wrd >> (sh + 9)) & 1u) ? fmaxf(u3.x, u3.y) : 0.f;
                dacc[i] += (p0 + p1) + (p2 + p3);
                __half2 hlo = __floats2half2_rn(p0, p1);   // (k c2, c2+1)
                __half2 hhi = __floats2half2_rn(p2, p3);   // (k c2+8, c2+9)
                int base = (i >> 1) * 4;                    // tile half
                int ri = i & 1;                             // r vs r+8
                afr[base + ri]     = *(unsigned*)&hlo;      // a0/a1
                afr[base + 2 + ri] = *(unsigned*)&hhi;      // a2/a3
            }
            #pragma unroll
            for (int np = 0; np < 4; np++) {
                unsigned b0, b1, b2, b3;
                asm volatile("ldmatrix.sync.aligned.m8n8.x4.trans.shared.b16 {%0,%1,%2,%3}, [%4];"
                             : "=r"(b0), "=r"(b1), "=r"(b2), "=r"(b3)
                             : "r"(hbS + bsel * bufstride + ks * (16 * HBP * 2) + np * 32));
                mma16816(acc[0][np * 2],     afr[0], afr[1], afr[2], afr[3], b0, b1);
                mma16816(acc[0][np * 2 + 1], afr[0], afr[1], afr[2], afr[3], b2, b3);
                mma16816(acc[1][np * 2],     afr[4], afr[5], afr[6], afr[7], b0, b1);
                mma16816(acc[1][np * 2 + 1], afr[4], afr[5], afr[6], afr[7], b2, b3);
            }
        }
    }

    // quad-reduce row sums (each row's 64 k-cols live in 4 lanes)
    #pragma unroll
    for (int i = 0; i < 4; i++) {
        dacc[i] += __shfl_xor_sync(0xffffffffu, dacc[i], 1);
        dacc[i] += __shfl_xor_sync(0xffffffffu, dacc[i], 2);
    }
    const int pidx = (blockIdx.x * gridDim.y + head) * msplit + z;
    if ((lane & 3) == 0) {
        #pragma unroll
        for (int i = 0; i < 4; i++)
            g_pden[(size_t)pidx * BRR + w * 32 + rq + i * 8] = dacc[i];
    }

    float* np_ = g_pnum + (size_t)pidx * (BRR * HID);
    const int crow = w * 32 + (lane >> 2);
    const int ccol = (lane & 3) * 2;
    #pragma unroll
    for (int hh = 0; hh < 2; hh++) {
        #pragma unroll
        for (int nt = 0; nt < 8; nt++) {
            *(float2*)&np_[(size_t)(crow + hh * 16) * HID + nt * 8 + ccol] =
                make_float2(acc[hh][nt][0], acc[hh][nt][1]);
            *(float2*)&np_[(size_t)(crow + hh * 16 + 8) * HID + nt * 8 + ccol] =
                make_float2(acc[hh][nt][2], acc[hh][nt][3]);
        }
    }
}

// ---------------- 5. combine partials -> dest (divide + optional ELU) ----------------
__global__ void combine_kernel(float* __restrict__ dest, int msplit,
                               int ostride, int doElu, int useBuf) {
    const int rb = blockIdx.x, head = blockIdx.y, H = gridDim.y;
    float* obase = useBuf ? g_buf : dest;
    const int base = (rb * H + head) * msplit;
    for (int idx = threadIdx.x; idx < BRR * HID; idx += 256) {
        int row = idx >> 6;
        float num = 0.f, den = 0.f;
        for (int zz = 0; zz < msplit; zz++) {
            num += g_pnum[(size_t)(base + zz) * (BRR * HID) + idx];
            den += g_pden[(size_t)(base + zz) * BRR + row];
        }
        float t = num / den;
        if (doElu) t = (t > 0.f) ? t : expm1f(t);
        obase[(size_t)(rb * BRR + row) * ostride + head * HID + (idx & 63)] = t;
    }
}

// ---------------- launch ----------------
extern "C" void kernel_launch(void* const* d_in, const int* in_sizes, int n_in,
                              void* d_out, int out_size) {
    const float* x   = (const float*)d_in[0];
    const int*   adj = (const int*)d_in[1];
    const float* W0  = (const float*)d_in[2];
    const float* a0  = (const float*)d_in[3];
    const float* W1  = (const float*)d_in[4];
    const float* a1  = (const float*)d_in[5];
    const float* W2  = (const float*)d_in[6];
    const float* a2  = (const float*)d_in[7];
    float* out = (float*)d_out;

    pack_adj_kernel<<<NROWS, 128>>>(adj);

    // layer 0: D=128, H=4, msplit=2
    gemm_kernel<<<dim3(64, 4), 256>>>(x, W0, 128, 0);
    compute_e_kernel<<<4 * 512, 256>>>(a0, 4);
    attn_kernel<<<dim3(32, 4, 2), 128>>>();
    combine_kernel<<<dim3(32, 4), 256>>>(nullptr, 2, 256, 1, 1);

    // layer 1: D=256, H=4, msplit=2
    gemm_kernel<<<dim3(64, 4), 256>>>(nullptr, W1, 256, 1);
    compute_e_kernel<<<4 * 512, 256>>>(a1, 4);
    attn_kernel<<<dim3(32, 4, 2), 128>>>();
    combine_kernel<<<dim3(32, 4), 256>>>(nullptr, 2, 256, 1, 1);

    // layer 2: D=256, H=1, msplit=8
    gemm_kernel<<<dim3(64, 1), 256>>>(nullptr, W2, 256, 1);
    compute_e_kernel<<<512, 256>>>(a2, 1);
    attn_kernel<<<dim3(32, 1, 8), 128>>>();
    combine_kernel<<<dim3(32, 1), 256>>>(out, 8, 64, 0, 0);
}

// round 12
// speedup vs baseline: 4.8383x; 1.0636x over previous
#include <cuda_runtime.h>
#include <cuda_fp16.h>
#include <math.h>

#define NROWS 4096
#define NW 128          // adjacency bitmask words per row
#define HID 64
#define ALPHA 0.2f
#define BRR 128         // attention rows per block
#define BM 64           // attention m-chunk
#define HBP 72          // h tile pitch in halves (144 B)
#define BUFBYTES (BM * HBP * 2)

// ---------------- device scratch ----------------
__device__ unsigned int g_adjbits[NROWS * NW];       // 2 MB packed adjacency
__device__ float g_h[4 * NROWS * HID];               // fp32 head features
__device__ __half g_h16[4 * NROWS * HID];            // fp16 head features (mma B)
__device__ float g_el[4 * NROWS];
__device__ float g_er[4 * NROWS];
__device__ unsigned int g_emax_u[4];                 // ordered-uint per-head max(e_r)
__device__ float g_buf[NROWS * 256];                 // inter-layer activations
__device__ float g_pnum[32 * 4 * 2 * BRR * HID];     // partial numerators
__device__ float g_pden[32 * 4 * 2 * BRR];           // partial denominators

// ---------------- helpers ----------------
__device__ __forceinline__ unsigned f2ord(float f) {
    unsigned u = __float_as_uint(f);
    return (u & 0x80000000u) ? ~u : (u | 0x80000000u);
}
__device__ __forceinline__ float ord2f(unsigned u) {
    return (u & 0x80000000u) ? __uint_as_float(u ^ 0x80000000u) : __uint_as_float(~u);
}
__device__ __forceinline__ unsigned long long packAC(float a, float c) {
    unsigned long long r;
    asm("mov.b64 %0, {%1, %2};" : "=l"(r) : "f"(a), "f"(c));
    return r;
}
__device__ __forceinline__ float2 mul2(unsigned long long a, unsigned long long b) {
    unsigned long long r;
    asm("mul.rn.f32x2 %0, %1, %2;" : "=l"(r) : "l"(a), "l"(b));
    float2 f;
    asm("mov.b64 {%0, %1}, %2;" : "=f"(f.x), "=f"(f.y) : "l"(r));
    return f;
}
__device__ __forceinline__ void mma16816(float* c, unsigned a0, unsigned a1,
                                         unsigned a2, unsigned a3,
                                         unsigned b0, unsigned b1) {
    asm volatile(
        "mma.sync.aligned.m16n8k16.row.col.f32.f16.f16.f32 "
        "{%0,%1,%2,%3}, {%4,%5,%6,%7}, {%8,%9}, {%0,%1,%2,%3};"
        : "+f"(c[0]), "+f"(c[1]), "+f"(c[2]), "+f"(c[3])
        : "r"(a0), "r"(a1), "r"(a2), "r"(a3), "r"(b0), "r"(b1));
}
__device__ __forceinline__ void cpasync16(unsigned dst, const void* src) {
    asm volatile("cp.async.cg.shared.global [%0], [%1], 16;" :: "r"(dst), "l"(src));
}

// ---------------- 1. pack adjacency into bitmask (+ emax reset for layer 0) ----------------
__global__ void pack_adj_kernel(const int* __restrict__ adj) {
    if (blockIdx.x == 0 && threadIdx.x < 4) g_emax_u[threadIdx.x] = 0u;
    int n = blockIdx.x;
    int warp = threadIdx.x >> 5, lane = threadIdx.x & 31;
    const int* row = adj + (size_t)n * NROWS;
    #pragma unroll 4
    for (int w = warp * 32; w < warp * 32 + 32; w++) {
        int v = row[w * 32 + lane];
        unsigned int bits = __ballot_sync(0xffffffffu, v > 0);
        if (lane == 0) g_adjbits[n * NW + w] = bits;
    }
}

// ---------------- 2. feature GEMM + fused e_l/e_r/emax epilogue ----------------
__global__ __launch_bounds__(256) void gemm_kernel(const float* __restrict__ Xext,
                                                   const float* __restrict__ W,
                                                   const float* __restrict__ a,
                                                   int D, int useBuf) {
    const float* __restrict__ X = useBuf ? (const float*)g_buf : Xext;
    const int head = blockIdx.y;
    const int r0 = blockIdx.x * 64;
    const int tid = threadIdx.x;
    __shared__ __align__(16) float Xs[64][33];
    __shared__ __align__(16) float Ws[32][64];
    float acc[4][4];
    #pragma unroll
    for (int r = 0; r < 4; r++)
        #pragma unroll
        for (int c = 0; c < 4; c++) acc[r][c] = 0.f;

    const int fr = tid >> 4, cg = tid & 15;
    const float* Wh = W + (size_t)head * D * HID;

    for (int d0 = 0; d0 < D; d0 += 32) {
        {
            int j = tid & 31, n0 = (tid >> 5) * 8;
            #pragma unroll
            for (int i = 0; i < 8; i++)
                Xs[n0 + i][j] = X[(size_t)(r0 + n0 + i) * D + d0 + j];
        }
        {
            int o = tid & 63, j0 = (tid >> 6) * 8;
            #pragma unroll
            for (int i = 0; i < 8; i++)
                Ws[j0 + i][o] = Wh[(size_t)(d0 + j0 + i) * HID + o];
        }
        __syncthreads();
        #pragma unroll
        for (int k = 0; k < 32; k++) {
            float4 wv = *(const float4*)&Ws[k][cg * 4];
            float x0 = Xs[fr * 4 + 0][k];
            float x1 = Xs[fr * 4 + 1][k];
            float x2 = Xs[fr * 4 + 2][k];
            float x3 = Xs[fr * 4 + 3][k];
            acc[0][0] += x0 * wv.x; acc[0][1] += x0 * wv.y; acc[0][2] += x0 * wv.z; acc[0][3] += x0 * wv.w;
            acc[1][0] += x1 * wv.x; acc[1][1] += x1 * wv.y; acc[1][2] += x1 * wv.z; acc[1][3] += x1 * wv.w;
            acc[2][0] += x2 * wv.x; acc[2][1] += x2 * wv.y; acc[2][2] += x2 * wv.z; acc[2][3] += x2 * wv.w;
            acc[3][0] += x3 * wv.x; acc[3][1] += x3 * wv.y; acc[3][2] += x3 * wv.z; acc[3][3] += x3 * wv.w;
        }
        __syncthreads();
    }
    float* hp = g_h + ((size_t)head * NROWS + r0) * HID;
    __half2* hp16 = (__half2*)(g_h16 + ((size_t)head * NROWS + r0) * HID);
    #pragma unroll
    for (int r = 0; r < 4; r++) {
        int rr = fr * 4 + r;
        *(float4*)&hp[(size_t)rr * HID + cg * 4] =
            make_float4(acc[r][0], acc[r][1], acc[r][2], acc[r][3]);
        hp16[rr * 32 + cg * 2]     = __floats2half2_rn(acc[r][0], acc[r][1]);
        hp16[rr * 32 + cg * 2 + 1] = __floats2half2_rn(acc[r][2], acc[r][3]);
    }

    // fused e_l / e_r: dot own 4 cols with a_l/a_r, reduce across 16-lane cg group
    const float* ah = a + head * 2 * HID;
    float4 al = *(const float4*)&ah[cg * 4];
    float4 ar = *(const float4*)&ah[HID + cg * 4];
    float* erow = (float*)Xs;   // reuse (all loop reads done)
    #pragma unroll
    for (int r = 0; r < 4; r++) {
        float pl = acc[r][0] * al.x + acc[r][1] * al.y + acc[r][2] * al.z + acc[r][3] * al.w;
        float pr = acc[r][0] * ar.x + acc[r][1] * ar.y + acc[r][2] * ar.z + acc[r][3] * ar.w;
        #pragma unroll
        for (int off = 8; off; off >>= 1) {
            pl += __shfl_xor_sync(0xffffffffu, pl, off);
            pr += __shfl_xor_sync(0xffffffffu, pr, off);
        }
        if (cg == 0) {
            int rr = fr * 4 + r;
            g_el[head * NROWS + r0 + rr] = pl;
            g_er[head * NROWS + r0 + rr] = pr;
            erow[rr] = pr;
        }
    }
    __syncthreads();
    if (tid == 0) {
        float m = erow[0];
        #pragma unroll
        for (int i = 1; i < 64; i++) m = fmaxf(m, erow[i]);
        atomicMax(&g_emax_u[head], f2ord(m));
    }
}

// ---------------- 3. fused attention: in-register A frags + mma.sync + cp.async pipeline ----------------
// 128 threads (4 warps). 128x64 tile; warp w owns rows w*32..w*32+31.
__global__ __launch_bounds__(128, 3) void attn_kernel() {
    const int head = blockIdx.y;
    const int r0b = blockIdx.x * BRR;
    const int z = blockIdx.z;
    const int msplit = gridDim.z;
    const int mlen = NROWS / msplit;
    const int mstart = z * mlen;
    const int tid = threadIdx.x;
    const int lane = tid & 31, w = tid >> 5;

    __shared__ __align__(16) __half hsB[3][BM * HBP];  // triple-buffered h tile (27.6 KB)
    __shared__ __align__(16) float2 bd[2048];          // per-column (B, D) (16 KB max)

    // per-column (B, D) = (exp(er-emax), exp(alpha*(er-emax)))
    const float emax = ord2f(g_emax_u[head]);
    for (int i = tid; i < mlen; i += 128) {
        float t = g_er[head * NROWS + mstart + i] - emax;
        bd[i] = make_float2(__expf(t), __expf(ALPHA * t));
    }

    // 4 owned score rows: w*32 + (lane>>2) + {0,8,16,24}
    const int rq = lane >> 2;
    const int c2 = (lane & 3) * 2;
    unsigned long long AC[4];
    float dacc[4];
    const unsigned* awp[4];
    #pragma unroll
    for (int i = 0; i < 4; i++) {
        int rowi = w * 32 + rq + i * 8;
        float el = g_el[head * NROWS + r0b + rowi];
        float s0 = el + emax;
        float M = fmaxf(s0, ALPHA * s0);       // per-row shift (num & den consistent)
        AC[i] = packAC(__expf(s0 - M), __expf(ALPHA * s0 - M));
        dacc[i] = 0.f;
        awp[i] = g_adjbits + (size_t)(r0b + rowi) * NW;
    }

    float acc[2][8][4];
    #pragma unroll
    for (int hh = 0; hh < 2; hh++)
        #pragma unroll
        for (int nt = 0; nt < 8; nt++)
            #pragma unroll
            for (int c = 0; c < 4; c++) acc[hh][nt][c] = 0.f;

    const __half* hb16 = g_h16 + (size_t)head * NROWS * HID;

    // B ldmatrix base (verified mapping)
    const int grp = lane >> 3, li = lane & 7;
    const unsigned hbS = (unsigned)__cvta_generic_to_shared(
        &hsB[0][((grp & 1) * 8 + li) * HBP + (grp >> 1) * 8]);

    // cp.async staging: 4x 16B per thread per chunk
    int srow[4], sc8[4];
    unsigned sdst[4];
    const unsigned hsBS = (unsigned)__cvta_generic_to_shared(&hsB[0][0]);
    #pragma unroll
    for (int i = 0; i < 4; i++) {
        int idx = tid + i * 128;
        srow[i] = idx >> 3;
        sc8[i] = (idx & 7) * 8;
        sdst[i] = hsBS + (unsigned)((srow[i] * HBP + sc8[i]) * 2);
    }

    const int NCHUNK = mlen / BM;

    // prologue: stage chunk 0 into buffer 0
    #pragma unroll
    for (int i = 0; i < 4; i++)
        cpasync16(sdst[i], &hb16[(size_t)(mstart + srow[i]) * HID + sc8[i]]);
    asm volatile("cp.async.commit_group;" ::: "memory");

    __syncthreads();   // bd ready

    int cur = 0;
    for (int ci = 0; ci < NCHUNK; ci++) {
        const int m0 = mstart + ci * BM;
        const int nxt = (cur == 2) ? 0 : cur + 1;
        // issue next chunk's copy (into buffer computed-on 2 chunks ago: fenced by barriers)
        if (ci + 1 < NCHUNK) {
            #pragma unroll
            for (int i = 0; i < 4; i++)
                cpasync16(sdst[i] + (unsigned)(nxt * BUFBYTES),
                          &hb16[(size_t)(m0 + BM + srow[i]) * HID + sc8[i]]);
        }
        asm volatile("cp.async.commit_group;" ::: "memory");
        // adjacency words for my 4 rows (independent of smem wait)
        uint2 aj[4];
        #pragma unroll
        for (int i = 0; i < 4; i++) aj[i] = *(const uint2*)(awp[i] + (m0 >> 5));
        asm volatile("cp.async.wait_group 1;" ::: "memory");
        __syncthreads();   // chunk ci's tile visible to all

        const float4* bd4 = (const float4*)(bd + (m0 - mstart));
        const unsigned hbC = hbS + (unsigned)(cur * BUFBYTES);
        #pragma unroll
        for (int ks = 0; ks < 4; ks++) {
            float4 q0 = bd4[ks * 8 + (lane & 3)];        // (B,D) for k=c2, c2+1
            float4 q1 = bd4[ks * 8 + 4 + (lane & 3)];    // (B,D) for k=c2+8, c2+9
            unsigned afr[8];
            #pragma unroll
            for (int i = 0; i < 4; i++) {
                unsigned wrd = (ks < 2) ? aj[i].x : aj[i].y;
                int sh = (ks & 1) * 16 + c2;
                float2 u0 = mul2(AC[i], *(const unsigned long long*)&q0.x);
                float2 u1 = mul2(AC[i], *(const unsigned long long*)&q0.z);
                float2 u2 = mul2(AC[i], *(const unsigned long long*)&q1.x);
                float2 u3 = mul2(AC[i], *(const unsigned long long*)&q1.z);
                float p0 = ((wrd >> sh) & 1u)       ? fmaxf(u0.x, u0.y) : 0.f;
                float p1 = ((wrd >> (sh + 1)) & 1u) ? fmaxf(u1.x, u1.y) : 0.f;
                float p2 = ((wrd >> (sh + 8)) & 1u) ? fmaxf(u2.x, u2.y) : 0.f;
                float p3 = ((wrd >> (sh + 9)) & 1u) ? fmaxf(u3.x, u3.y) : 0.f;
                dacc[i] += (p0 + p1) + (p2 + p3);
                __half2 hlo = __floats2half2_rn(p0, p1);
                __half2 hhi = __floats2half2_rn(p2, p3);
                int base = (i >> 1) * 4;
                int ri = i & 1;
                afr[base + ri]     = *(unsigned*)&hlo;
                afr[base + 2 + ri] = *(unsigned*)&hhi;
            }
            #pragma unroll
            for (int np = 0; np < 4; np++) {
                unsigned b0, b1, b2, b3;
                asm volatile("ldmatrix.sync.aligned.m8n8.x4.trans.shared.b16 {%0,%1,%2,%3}, [%4];"
                             : "=r"(b0), "=r"(b1), "=r"(b2), "=r"(b3)
                             : "r"(hbC + ks * (16 * HBP * 2) + np * 32));
                mma16816(acc[0][np * 2],     afr[0], afr[1], afr[2], afr[3], b0, b1);
                mma16816(acc[0][np * 2 + 1], afr[0], afr[1], afr[2], afr[3], b2, b3);
                mma16816(acc[1][np * 2],     afr[4], afr[5], afr[6], afr[7], b0, b1);
                mma16816(acc[1][np * 2 + 1], afr[4], afr[5], afr[6], afr[7], b2, b3);
            }
        }
        cur = nxt;
    }

    // quad-reduce row sums
    #pragma unroll
    for (int i = 0; i < 4; i++) {
        dacc[i] += __shfl_xor_sync(0xffffffffu, dacc[i], 1);
        dacc[i] += __shfl_xor_sync(0xffffffffu, dacc[i], 2);
    }
    const int pidx = (blockIdx.x * gridDim.y + head) * msplit + z;
    if ((lane & 3) == 0) {
        #pragma unroll
        for (int i = 0; i < 4; i++)
            g_pden[(size_t)pidx * BRR + w * 32 + rq + i * 8] = dacc[i];
    }

    float* np_ = g_pnum + (size_t)pidx * (BRR * HID);
    const int crow = w * 32 + (lane >> 2);
    const int ccol = (lane & 3) * 2;
    #pragma unroll
    for (int hh = 0; hh < 2; hh++) {
        #pragma unroll
        for (int nt = 0; nt < 8; nt++) {
            *(float2*)&np_[(size_t)(crow + hh * 16) * HID + nt * 8 + ccol] =
                make_float2(acc[hh][nt][0], acc[hh][nt][1]);
            *(float2*)&np_[(size_t)(crow + hh * 16 + 8) * HID + nt * 8 + ccol] =
                make_float2(acc[hh][nt][2], acc[hh][nt][3]);
        }
    }
}

// ---------------- 4. combine partials -> dest (divide + optional ELU; resets emax for next layer) ----------------
__global__ void combine_kernel(float* __restrict__ dest, int msplit,
                               int ostride, int doElu, int useBuf) {
    if (blockIdx.x == 0 && blockIdx.y == 0 && threadIdx.x < 4) g_emax_u[threadIdx.x] = 0u;
    const int rb = blockIdx.x, head = blockIdx.y, H = gridDim.y;
    float* obase = useBuf ? g_buf : dest;
    const int base = (rb * H + head) * msplit;
    for (int idx = threadIdx.x; idx < BRR * HID; idx += 256) {
        int row = idx >> 6;
        float num = 0.f, den = 0.f;
        for (int zz = 0; zz < msplit; zz++) {
            num += g_pnum[(size_t)(base + zz) * (BRR * HID) + idx];
            den += g_pden[(size_t)(base + zz) * BRR + row];
        }
        float t = num / den;
        if (doElu) t = (t > 0.f) ? t : expm1f(t);
        obase[(size_t)(rb * BRR + row) * ostride + head * HID + (idx & 63)] = t;
    }
}

// ---------------- launch ----------------
extern "C" void kernel_launch(void* const* d_in, const int* in_sizes, int n_in,
                              void* d_out, int out_size) {
    const float* x   = (const float*)d_in[0];
    const int*   adj = (const int*)d_in[1];
    const float* W0  = (const float*)d_in[2];
    const float* a0  = (const float*)d_in[3];
    const float* W1  = (const float*)d_in[4];
    const float* a1  = (const float*)d_in[5];
    const float* W2  = (const float*)d_in[6];
    const float* a2  = (const float*)d_in[7];
    float* out = (float*)d_out;

    pack_adj_kernel<<<NROWS, 128>>>(adj);

    // layer 0: D=128, H=4, msplit=2
    gemm_kernel<<<dim3(64, 4), 256>>>(x, W0, a0, 128, 0);
    attn_kernel<<<dim3(32, 4, 2), 128>>>();
    combine_kernel<<<dim3(32, 4), 256>>>(nullptr, 2, 256, 1, 1);

    // layer 1: D=256, H=4, msplit=2
    gemm_kernel<<<dim3(64, 4), 256>>>(nullptr, W1, a1, 256, 1);
    attn_kernel<<<dim3(32, 4, 2), 128>>>();
    combine_kernel<<<dim3(32, 4), 256>>>(nullptr, 2, 256, 1, 1);

    // layer 2: D=256, H=1, msplit=8
    gemm_kernel<<<dim3(64, 1), 256>>>(nullptr, W2, a2, 256, 1);
    attn_kernel<<<dim3(32, 1, 8), 128>>>();
    combine_kernel<<<dim3(32, 1), 256>>>(out, 8, 64, 0, 0);
}

// round 13
// speedup vs baseline: 5.8665x; 1.2125x over previous
#include <cuda_runtime.h>
#include <cuda_fp16.h>
#include <math.h>

#define NROWS 4096
#define NW 128          // adjacency bitmask words per row
#define HID 64
#define ALPHA 0.2f
#define BRR 64          // attention rows per block
#define BM 64           // attention m-chunk
#define HBP 72          // h tile pitch in halves (144 B)
#define BUFBYTES (BM * HBP * 2)

// ---------------- device scratch ----------------
__device__ unsigned int g_adjbits[NROWS * NW];       // 2 MB packed adjacency
__device__ float g_h[4 * NROWS * HID];               // fp32 head features
__device__ __half g_h16[4 * NROWS * HID];            // fp16 head features (mma B)
__device__ float g_el[4 * NROWS];
__device__ float g_er[4 * NROWS];
__device__ unsigned int g_emax_u[12];                // per (layer, head) max(e_r), ordered-uint
__device__ float g_buf[NROWS * 256];                 // inter-layer activations
__device__ float g_pnum[64 * 4 * BRR * HID];         // layer-2 partial numerators
__device__ float g_pden[64 * 4 * BRR];               // layer-2 partial denominators

// ---------------- helpers ----------------
__device__ __forceinline__ unsigned f2ord(float f) {
    unsigned u = __float_as_uint(f);
    return (u & 0x80000000u) ? ~u : (u | 0x80000000u);
}
__device__ __forceinline__ float ord2f(unsigned u) {
    return (u & 0x80000000u) ? __uint_as_float(u ^ 0x80000000u) : __uint_as_float(~u);
}
__device__ __forceinline__ unsigned long long packAC(float a, float c) {
    unsigned long long r;
    asm("mov.b64 %0, {%1, %2};" : "=l"(r) : "f"(a), "f"(c));
    return r;
}
__device__ __forceinline__ float2 mul2(unsigned long long a, unsigned long long b) {
    unsigned long long r;
    asm("mul.rn.f32x2 %0, %1, %2;" : "=l"(r) : "l"(a), "l"(b));
    float2 f;
    asm("mov.b64 {%0, %1}, %2;" : "=f"(f.x), "=f"(f.y) : "l"(r));
    return f;
}
__device__ __forceinline__ void mma16816(float* c, unsigned a0, unsigned a1,
                                         unsigned a2, unsigned a3,
                                         unsigned b0, unsigned b1) {
    asm volatile(
        "mma.sync.aligned.m16n8k16.row.col.f32.f16.f16.f32 "
        "{%0,%1,%2,%3}, {%4,%5,%6,%7}, {%8,%9}, {%0,%1,%2,%3};"
        : "+f"(c[0]), "+f"(c[1]), "+f"(c[2]), "+f"(c[3])
        : "r"(a0), "r"(a1), "r"(a2), "r"(a3), "r"(b0), "r"(b1));
}
__device__ __forceinline__ void cpasync16(unsigned dst, const void* src) {
    asm volatile("cp.async.cg.shared.global [%0], [%1], 16;" :: "r"(dst), "l"(src));
}

// ---------------- 1. pack adjacency into bitmask (+ emax reset, all layers) ----------------
__global__ void pack_adj_kernel(const int* __restrict__ adj) {
    if (blockIdx.x == 0 && threadIdx.x < 12) g_emax_u[threadIdx.x] = 0u;
    int n = blockIdx.x;
    int warp = threadIdx.x >> 5, lane = threadIdx.x & 31;
    const int* row = adj + (size_t)n * NROWS;
    #pragma unroll 4
    for (int w = warp * 32; w < warp * 32 + 32; w++) {
        int v = row[w * 32 + lane];
        unsigned int bits = __ballot_sync(0xffffffffu, v > 0);
        if (lane == 0) g_adjbits[n * NW + w] = bits;
    }
}

// ---------------- 2. feature GEMM + fused e_l/e_r/emax epilogue ----------------
__global__ __launch_bounds__(256) void gemm_kernel(const float* __restrict__ Xext,
                                                   const float* __restrict__ W,
                                                   const float* __restrict__ a,
                                                   int D, int useBuf, int layer) {
    const float* __restrict__ X = useBuf ? (const float*)g_buf : Xext;
    const int head = blockIdx.y;
    const int r0 = blockIdx.x * 64;
    const int tid = threadIdx.x;
    __shared__ __align__(16) float Xs[64][33];
    __shared__ __align__(16) float Ws[32][64];
    float acc[4][4];
    #pragma unroll
    for (int r = 0; r < 4; r++)
        #pragma unroll
        for (int c = 0; c < 4; c++) acc[r][c] = 0.f;

    const int fr = tid >> 4, cg = tid & 15;
    const float* Wh = W + (size_t)head * D * HID;

    for (int d0 = 0; d0 < D; d0 += 32) {
        {
            int j = tid & 31, n0 = (tid >> 5) * 8;
            #pragma unroll
            for (int i = 0; i < 8; i++)
                Xs[n0 + i][j] = X[(size_t)(r0 + n0 + i) * D + d0 + j];
        }
        {
            int o = tid & 63, j0 = (tid >> 6) * 8;
            #pragma unroll
            for (int i = 0; i < 8; i++)
                Ws[j0 + i][o] = Wh[(size_t)(d0 + j0 + i) * HID + o];
        }
        __syncthreads();
        #pragma unroll
        for (int k = 0; k < 32; k++) {
            float4 wv = *(const float4*)&Ws[k][cg * 4];
            float x0 = Xs[fr * 4 + 0][k];
            float x1 = Xs[fr * 4 + 1][k];
            float x2 = Xs[fr * 4 + 2][k];
            float x3 = Xs[fr * 4 + 3][k];
            acc[0][0] += x0 * wv.x; acc[0][1] += x0 * wv.y; acc[0][2] += x0 * wv.z; acc[0][3] += x0 * wv.w;
            acc[1][0] += x1 * wv.x; acc[1][1] += x1 * wv.y; acc[1][2] += x1 * wv.z; acc[1][3] += x1 * wv.w;
            acc[2][0] += x2 * wv.x; acc[2][1] += x2 * wv.y; acc[2][2] += x2 * wv.z; acc[2][3] += x2 * wv.w;
            acc[3][0] += x3 * wv.x; acc[3][1] += x3 * wv.y; acc[3][2] += x3 * wv.z; acc[3][3] += x3 * wv.w;
        }
        __syncthreads();
    }
    float* hp = g_h + ((size_t)head * NROWS + r0) * HID;
    __half2* hp16 = (__half2*)(g_h16 + ((size_t)head * NROWS + r0) * HID);
    #pragma unroll
    for (int r = 0; r < 4; r++) {
        int rr = fr * 4 + r;
        *(float4*)&hp[(size_t)rr * HID + cg * 4] =
            make_float4(acc[r][0], acc[r][1], acc[r][2], acc[r][3]);
        hp16[rr * 32 + cg * 2]     = __floats2half2_rn(acc[r][0], acc[r][1]);
        hp16[rr * 32 + cg * 2 + 1] = __floats2half2_rn(acc[r][2], acc[r][3]);
    }

    // fused e_l / e_r: dot own 4 cols with a_l/a_r, reduce across 16-lane cg group
    const float* ah = a + head * 2 * HID;
    float4 al = *(const float4*)&ah[cg * 4];
    float4 ar = *(const float4*)&ah[HID + cg * 4];
    float* erow = (float*)Xs;   // reuse (all loop reads done)
    #pragma unroll
    for (int r = 0; r < 4; r++) {
        float pl = acc[r][0] * al.x + acc[r][1] * al.y + acc[r][2] * al.z + acc[r][3] * al.w;
        float pr = acc[r][0] * ar.x + acc[r][1] * ar.y + acc[r][2] * ar.z + acc[r][3] * ar.w;
        #pragma unroll
        for (int off = 8; off; off >>= 1) {
            pl += __shfl_xor_sync(0xffffffffu, pl, off);
            pr += __shfl_xor_sync(0xffffffffu, pr, off);
        }
        if (cg == 0) {
            int rr = fr * 4 + r;
            g_el[head * NROWS + r0 + rr] = pl;
            g_er[head * NROWS + r0 + rr] = pr;
            erow[rr] = pr;
        }
    }
    __syncthreads();
    if (tid == 0) {
        float m = erow[0];
        #pragma unroll
        for (int i = 1; i < 64; i++) m = fmaxf(m, erow[i]);
        atomicMax(&g_emax_u[layer * 4 + head], f2ord(m));
    }
}

// ---------------- 3. fused attention: 64-row tile, in-register A frags, cp.async pipeline ----------------
// 128 threads (4 warps). Warp w owns rows w*16..w*16+15.
// partial=0: writes final (divide + optional ELU) to dest/g_buf. partial=1: writes num/den.
__global__ __launch_bounds__(128, 3) void attn_kernel(float* __restrict__ dest, int layer,
                                                      int ostride, int doElu,
                                                      int toBuf, int partial) {
    const int head = blockIdx.y;
    const int r0b = blockIdx.x * BRR;
    const int z = blockIdx.z;
    const int msplit = gridDim.z;
    const int mlen = NROWS / msplit;
    const int mstart = z * mlen;
    const int tid = threadIdx.x;
    const int lane = tid & 31, w = tid >> 5;

    __shared__ __align__(16) __half hsB[3][BM * HBP];  // triple-buffered h tile (27.6 KB)
    __shared__ __align__(16) float2 bd[4096];          // per-column (B, D) (32 KB max)

    // per-column (B, D) = (exp(er-emax), exp(alpha*(er-emax)))
    const float emax = ord2f(g_emax_u[layer * 4 + head]);
    for (int i = tid; i < mlen; i += 128) {
        float t = g_er[head * NROWS + mstart + i] - emax;
        bd[i] = make_float2(__expf(t), __expf(ALPHA * t));
    }

    // 2 owned score rows: w*16 + rq + {0, 8}
    const int rq = lane >> 2;
    const int c2 = (lane & 3) * 2;
    unsigned long long AC[2];
    float dacc[2];
    const unsigned* awp[2];
    #pragma unroll
    for (int i = 0; i < 2; i++) {
        int rowi = w * 16 + rq + i * 8;
        float el = g_el[head * NROWS + r0b + rowi];
        float s0 = el + emax;
        float M = fmaxf(s0, ALPHA * s0);       // per-row shift (num & den consistent)
        AC[i] = packAC(__expf(s0 - M), __expf(ALPHA * s0 - M));
        dacc[i] = 0.f;
        awp[i] = g_adjbits + (size_t)(r0b + rowi) * NW;
    }

    float acc[8][4];
    #pragma unroll
    for (int nt = 0; nt < 8; nt++)
        #pragma unroll
        for (int c = 0; c < 4; c++) acc[nt][c] = 0.f;

    const __half* hb16 = g_h16 + (size_t)head * NROWS * HID;

    // B ldmatrix base (verified mapping)
    const int grp = lane >> 3, li = lane & 7;
    const unsigned hbS = (unsigned)__cvta_generic_to_shared(
        &hsB[0][((grp & 1) * 8 + li) * HBP + (grp >> 1) * 8]);

    // cp.async staging: 4x 16B per thread per chunk
    int srow[4], sc8[4];
    unsigned sdst[4];
    const unsigned hsBS = (unsigned)__cvta_generic_to_shared(&hsB[0][0]);
    #pragma unroll
    for (int i = 0; i < 4; i++) {
        int idx = tid + i * 128;
        srow[i] = idx >> 3;
        sc8[i] = (idx & 7) * 8;
        sdst[i] = hsBS + (unsigned)((srow[i] * HBP + sc8[i]) * 2);
    }

    const int NCHUNK = mlen / BM;

    // prologue: stage chunk 0 into buffer 0
    #pragma unroll
    for (int i = 0; i < 4; i++)
        cpasync16(sdst[i], &hb16[(size_t)(mstart + srow[i]) * HID + sc8[i]]);
    asm volatile("cp.async.commit_group;" ::: "memory");

    __syncthreads();   // bd ready

    int cur = 0;
    for (int ci = 0; ci < NCHUNK; ci++) {
        const int m0 = mstart + ci * BM;
        const int nxt = (cur == 2) ? 0 : cur + 1;
        if (ci + 1 < NCHUNK) {
            #pragma unroll
            for (int i = 0; i < 4; i++)
                cpasync16(sdst[i] + (unsigned)(nxt * BUFBYTES),
                          &hb16[(size_t)(m0 + BM + srow[i]) * HID + sc8[i]]);
        }
        asm volatile("cp.async.commit_group;" ::: "memory");
        uint2 aj[2];
        #pragma unroll
        for (int i = 0; i < 2; i++) aj[i] = *(const uint2*)(awp[i] + (m0 >> 5));
        asm volatile("cp.async.wait_group 1;" ::: "memory");
        __syncthreads();   // chunk ci's tile visible

        const float4* bd4 = (const float4*)(bd + (m0 - mstart));
        const unsigned hbC = hbS + (unsigned)(cur * BUFBYTES);
        #pragma unroll
        for (int ks = 0; ks < 4; ks++) {
            float4 q0 = bd4[ks * 8 + (lane & 3)];        // (B,D) for k=c2, c2+1
            float4 q1 = bd4[ks * 8 + 4 + (lane & 3)];    // (B,D) for k=c2+8, c2+9
            unsigned afr[4];
            #pragma unroll
            for (int i = 0; i < 2; i++) {
                unsigned wrd = (ks < 2) ? aj[i].x : aj[i].y;
                int sh = (ks & 1) * 16 + c2;
                float2 u0 = mul2(AC[i], *(const unsigned long long*)&q0.x);
                float2 u1 = mul2(AC[i], *(const unsigned long long*)&q0.z);
                float2 u2 = mul2(AC[i], *(const unsigned long long*)&q1.x);
                float2 u3 = mul2(AC[i], *(const unsigned long long*)&q1.z);
                float p0 = ((wrd >> sh) & 1u)       ? fmaxf(u0.x, u0.y) : 0.f;
                float p1 = ((wrd >> (sh + 1)) & 1u) ? fmaxf(u1.x, u1.y) : 0.f;
                float p2 = ((wrd >> (sh + 8)) & 1u) ? fmaxf(u2.x, u2.y) : 0.f;
                float p3 = ((wrd >> (sh + 9)) & 1u) ? fmaxf(u3.x, u3.y) : 0.f;
                dacc[i] += (p0 + p1) + (p2 + p3);
                __half2 hlo = __floats2half2_rn(p0, p1);
                __half2 hhi = __floats2half2_rn(p2, p3);
                afr[i]     = *(unsigned*)&hlo;      // rows rq / rq+8, k lo
                afr[2 + i] = *(unsigned*)&hhi;      // rows rq / rq+8, k hi
            }
            #pragma unroll
            for (int np = 0; np < 4; np++) {
                unsigned b0, b1, b2, b3;
                asm volatile("ldmatrix.sync.aligned.m8n8.x4.trans.shared.b16 {%0,%1,%2,%3}, [%4];"
                             : "=r"(b0), "=r"(b1), "=r"(b2), "=r"(b3)
                             : "r"(hbC + ks * (16 * HBP * 2) + np * 32));
                mma16816(acc[np * 2],     afr[0], afr[1], afr[2], afr[3], b0, b1);
                mma16816(acc[np * 2 + 1], afr[0], afr[1], afr[2], afr[3], b2, b3);
            }
        }
        cur = nxt;
    }

    // quad-reduce row sums (all 4 lanes of the quad end with the full sum)
    #pragma unroll
    for (int i = 0; i < 2; i++) {
        dacc[i] += __shfl_xor_sync(0xffffffffu, dacc[i], 1);
        dacc[i] += __shfl_xor_sync(0xffffffffu, dacc[i], 2);
    }

    const int crow = w * 16 + (lane >> 2);
    const int ccol = (lane & 3) * 2;

    if (!partial) {
        float* obase = toBuf ? g_buf : dest;
        const float inv0 = 1.0f / dacc[0];
        const float inv1 = 1.0f / dacc[1];
        #pragma unroll
        for (int nt = 0; nt < 8; nt++) {
            float v0 = acc[nt][0] * inv0, v1 = acc[nt][1] * inv0;
            float v2 = acc[nt][2] * inv1, v3 = acc[nt][3] * inv1;
            if (doElu) {
                v0 = (v0 > 0.f) ? v0 : expm1f(v0);
                v1 = (v1 > 0.f) ? v1 : expm1f(v1);
                v2 = (v2 > 0.f) ? v2 : expm1f(v2);
                v3 = (v3 > 0.f) ? v3 : expm1f(v3);
            }
            *(float2*)&obase[(size_t)(r0b + crow) * ostride + head * HID + nt * 8 + ccol] =
                make_float2(v0, v1);
            *(float2*)&obase[(size_t)(r0b + crow + 8) * ostride + head * HID + nt * 8 + ccol] =
                make_float2(v2, v3);
        }
    } else {
        const int pidx = (blockIdx.x * gridDim.y + head) * msplit + z;
        if ((lane & 3) == 0) {
            #pragma unroll
            for (int i = 0; i < 2; i++)
                g_pden[(size_t)pidx * BRR + w * 16 + rq + i * 8] = dacc[i];
        }
        float* np_ = g_pnum + (size_t)pidx * (BRR * HID);
        #pragma unroll
        for (int nt = 0; nt < 8; nt++) {
            *(float2*)&np_[(size_t)crow * HID + nt * 8 + ccol] =
                make_float2(acc[nt][0], acc[nt][1]);
            *(float2*)&np_[(size_t)(crow + 8) * HID + nt * 8 + ccol] =
                make_float2(acc[nt][2], acc[nt][3]);
        }
    }
}

// ---------------- 4. combine layer-2 partials -> out ----------------
__global__ void combine_kernel(float* __restrict__ dest, int msplit) {
    const int rb = blockIdx.x;
    const int base = rb * msplit;
    for (int idx = threadIdx.x; idx < BRR * HID; idx += 256) {
        int row = idx >> 6;
        float num = 0.f, den = 0.f;
        for (int zz = 0; zz < msplit; zz++) {
            num += g_pnum[(size_t)(base + zz) * (BRR * HID) + idx];
            den += g_pden[(size_t)(base + zz) * BRR + row];
        }
        dest[(size_t)(rb * BRR + row) * HID + (idx & 63)] = num / den;
    }
}

// ---------------- launch ----------------
extern "C" void kernel_launch(void* const* d_in, const int* in_sizes, int n_in,
                              void* d_out, int out_size) {
    const float* x   = (const float*)d_in[0];
    const int*   adj = (const int*)d_in[1];
    const float* W0  = (const float*)d_in[2];
    const float* a0  = (const float*)d_in[3];
    const float* W1  = (const float*)d_in[4];
    const float* a1  = (const float*)d_in[5];
    const float* W2  = (const float*)d_in[6];
    const float* a2  = (const float*)d_in[7];
    float* out = (float*)d_out;

    pack_adj_kernel<<<NROWS, 128>>>(adj);

    // layer 0: D=128, H=4, msplit=1, direct-write + ELU
    gemm_kernel<<<dim3(64, 4), 256>>>(x, W0, a0, 128, 0, 0);
    attn_kernel<<<dim3(64, 4, 1), 128>>>(nullptr, 0, 256, 1, 1, 0);

    // layer 1: D=256, H=4, msplit=1, direct-write + ELU
    gemm_kernel<<<dim3(64, 4), 256>>>(nullptr, W1, a1, 256, 1, 1);
    attn_kernel<<<dim3(64, 4, 1), 128>>>(nullptr, 1, 256, 1, 1, 0);

    // layer 2: D=256, H=1, msplit=4 partials + small combine
    gemm_kernel<<<dim3(64, 1), 256>>>(nullptr, W2, a2, 256, 1, 2);
    attn_kernel<<<dim3(64, 1, 4), 128>>>(nullptr, 2, 64, 0, 0, 1);
    combine_kernel<<<64, 256>>>(out, 4);
}

// round 14
// speedup vs baseline: 6.7399x; 1.1489x over previous
#include <cuda_runtime.h>
#include <cuda_fp16.h>
#include <math.h>

#define NROWS 4096
#define NW 128          // adjacency bitmask words per row
#define HID 64
#define ALPHA 0.2f
#define BRR 64          // attention rows per block
#define BM 64           // attention m-chunk
#define HBP 72          // attn h tile pitch in halves (144 B)
#define BUFBYTES (BM * HBP * 2)
#define XSP 40          // gemm A tile pitch in halves (80 B)
#define WSP 72          // gemm B tile pitch in halves (144 B)
#define XSB (64 * XSP)  // halves per A stage
#define WSB (32 * WSP)  // halves per B stage

// ---------------- device scratch ----------------
__device__ unsigned int g_adjbits[NROWS * NW];       // 2 MB packed adjacency
__device__ __half g_h16[4 * NROWS * HID];            // fp16 head features (mma B)
__device__ float g_el[4 * NROWS];
__device__ float g_er[4 * NROWS];
__device__ unsigned int g_emax_u[12];                // per (layer, head) max(e_r)
__device__ __half g_buf16[NROWS * 256];              // fp16 inter-layer activations
__device__ __half g_x16[NROWS * 128];                // fp16 copy of input x
__device__ __half g_W16[4 * 256 * 64 + 4 * 128 * 64 + 256 * 64];  // fp16 W0|W1|W2
__device__ float g_pnum[64 * 4 * BRR * HID];         // layer-2 partial numerators
__device__ float g_pden[64 * 4 * BRR];               // layer-2 partial denominators

#define W0OFF 0
#define W1OFF (4 * 128 * 64)
#define W2OFF (W1OFF + 4 * 256 * 64)

// ---------------- helpers ----------------
__device__ __forceinline__ unsigned f2ord(float f) {
    unsigned u = __float_as_uint(f);
    return (u & 0x80000000u) ? ~u : (u | 0x80000000u);
}
__device__ __forceinline__ float ord2f(unsigned u) {
    return (u & 0x80000000u) ? __uint_as_float(u ^ 0x80000000u) : __uint_as_float(~u);
}
__device__ __forceinline__ unsigned long long packAC(float a, float c) {
    unsigned long long r;
    asm("mov.b64 %0, {%1, %2};" : "=l"(r) : "f"(a), "f"(c));
    return r;
}
__device__ __forceinline__ float2 mul2(unsigned long long a, unsigned long long b) {
    unsigned long long r;
    asm("mul.rn.f32x2 %0, %1, %2;" : "=l"(r) : "l"(a), "l"(b));
    float2 f;
    asm("mov.b64 {%0, %1}, %2;" : "=f"(f.x), "=f"(f.y) : "l"(r));
    return f;
}
__device__ __forceinline__ void mma16816(float* c, unsigned a0, unsigned a1,
                                         unsigned a2, unsigned a3,
                                         unsigned b0, unsigned b1) {
    asm volatile(
        "mma.sync.aligned.m16n8k16.row.col.f32.f16.f16.f32 "
        "{%0,%1,%2,%3}, {%4,%5,%6,%7}, {%8,%9}, {%0,%1,%2,%3};"
        : "+f"(c[0]), "+f"(c[1]), "+f"(c[2]), "+f"(c[3])
        : "r"(a0), "r"(a1), "r"(a2), "r"(a3), "r"(b0), "r"(b1));
}
__device__ __forceinline__ void cpasync16(unsigned dst, const void* src) {
    asm volatile("cp.async.cg.shared.global [%0], [%1], 16;" :: "r"(dst), "l"(src));
}

// ---------------- 1. pack adjacency into bitmask (+ emax reset) ----------------
__global__ void pack_adj_kernel(const int* __restrict__ adj) {
    if (blockIdx.x == 0 && threadIdx.x < 12) g_emax_u[threadIdx.x] = 0u;
    int n = blockIdx.x;
    int warp = threadIdx.x >> 5, lane = threadIdx.x & 31;
    const int* row = adj + (size_t)n * NROWS;
    #pragma unroll 4
    for (int w = warp * 32; w < warp * 32 + 32; w++) {
        int v = row[w * 32 + lane];
        unsigned int bits = __ballot_sync(0xffffffffu, v > 0);
        if (lane == 0) g_adjbits[n * NW + w] = bits;
    }
}

// ---------------- 2. fp16 conversions of x and weights ----------------
__global__ void convert_kernel(const float* __restrict__ x,
                               const float* __restrict__ W0,
                               const float* __restrict__ W1,
                               const float* __restrict__ W2) {
    int t = blockIdx.x * blockDim.x + threadIdx.x;
    int stride = gridDim.x * blockDim.x;
    for (int i = t; i < NROWS * 128; i += stride) g_x16[i] = __float2half_rn(x[i]);
    for (int i = t; i < 4 * 128 * 64; i += stride) g_W16[W0OFF + i] = __float2half_rn(W0[i]);
    for (int i = t; i < 4 * 256 * 64; i += stride) g_W16[W1OFF + i] = __float2half_rn(W1[i]);
    for (int i = t; i < 256 * 64; i += stride) g_W16[W2OFF + i] = __float2half_rn(W2[i]);
}

// ---------------- 3. fp16 tensor-core feature GEMM + fused e epilogue ----------------
// 128 threads (4 warps), 64 rows x 64 cols per block; K chunked by 32, cp.async 3-buffer.
__global__ __launch_bounds__(128, 3) void gemm16_kernel(const __half* __restrict__ X16,
                                                        const __half* __restrict__ W16,
                                                        const float* __restrict__ a,
                                                        int D, int layer) {
    const int head = blockIdx.y;
    const int r0 = blockIdx.x * 64;
    const int tid = threadIdx.x;
    const int lane = tid & 31, w = tid >> 5;

    __shared__ __align__(16) __half Xs[3][XSB];   // A stages (15 KB)
    __shared__ __align__(16) __half Ws[3][WSB];   // B stages (13.8 KB)
    __shared__ float erow[64];

    float acc[8][4];
    #pragma unroll
    for (int nt = 0; nt < 8; nt++)
        #pragma unroll
        for (int c = 0; c < 4; c++) acc[nt][c] = 0.f;

    // ldmatrix bases (R5-verified mappings)
    const int grp = lane >> 3, li = lane & 7;
    const int arow = w * 16 + li + (grp & 1) * 8;
    const unsigned aS = (unsigned)__cvta_generic_to_shared(
        &Xs[0][arow * XSP + (grp >> 1) * 8]);
    const unsigned bS = (unsigned)__cvta_generic_to_shared(
        &Ws[0][((grp & 1) * 8 + li) * WSP + (grp >> 1) * 8]);

    // staging addresses: A 2x16B, B 2x16B per thread per chunk
    int axr[2], axc[2], bkr[2], bkc[2];
    unsigned adst[2], bdst[2];
    const unsigned XsS = (unsigned)__cvta_generic_to_shared(&Xs[0][0]);
    const unsigned WsS = (unsigned)__cvta_generic_to_shared(&Ws[0][0]);
    #pragma unroll
    for (int i = 0; i < 2; i++) {
        int idx = tid + i * 128;
        axr[i] = idx >> 2; axc[i] = (idx & 3) * 8;
        adst[i] = XsS + (unsigned)((axr[i] * XSP + axc[i]) * 2);
        bkr[i] = idx >> 3; bkc[i] = (idx & 7) * 8;
        bdst[i] = WsS + (unsigned)((bkr[i] * WSP + bkc[i]) * 2);
    }
    const __half* Wh = W16 + (size_t)head * D * HID;
    const int NCH = D / 32;

    // prologue: chunk 0 -> buffer 0
    #pragma unroll
    for (int i = 0; i < 2; i++) {
        cpasync16(adst[i], &X16[(size_t)(r0 + axr[i]) * D + axc[i]]);
        cpasync16(bdst[i], &Wh[(size_t)bkr[i] * HID + bkc[i]]);
    }
    asm volatile("cp.async.commit_group;" ::: "memory");

    int cur = 0;
    for (int ci = 0; ci < NCH; ci++) {
        const int k0 = ci * 32;
        const int nxt = (cur == 2) ? 0 : cur + 1;
        if (ci + 1 < NCH) {
            #pragma unroll
            for (int i = 0; i < 2; i++) {
                cpasync16(adst[i] + (unsigned)(nxt * XSB * 2),
                          &X16[(size_t)(r0 + axr[i]) * D + k0 + 32 + axc[i]]);
                cpasync16(bdst[i] + (unsigned)(nxt * WSB * 2),
                          &Wh[(size_t)(k0 + 32 + bkr[i]) * HID + bkc[i]]);
            }
        }
        asm volatile("cp.async.commit_group;" ::: "memory");
        asm volatile("cp.async.wait_group 1;" ::: "memory");
        __syncthreads();

        const unsigned aC = aS + (unsigned)(cur * XSB * 2);
        const unsigned bC = bS + (unsigned)(cur * WSB * 2);
        #pragma unroll
        for (int ks = 0; ks < 2; ks++) {
            unsigned a0, a1, a2, a3;
            asm volatile("ldmatrix.sync.aligned.m8n8.x4.shared.b16 {%0,%1,%2,%3}, [%4];"
                         : "=r"(a0), "=r"(a1), "=r"(a2), "=r"(a3)
                         : "r"(aC + ks * 32));
            #pragma unroll
            for (int np = 0; np < 4; np++) {
                unsigned b0, b1, b2, b3;
                asm volatile("ldmatrix.sync.aligned.m8n8.x4.trans.shared.b16 {%0,%1,%2,%3}, [%4];"
                             : "=r"(b0), "=r"(b1), "=r"(b2), "=r"(b3)
                             : "r"(bC + ks * (16 * WSP * 2) + np * 32));
                mma16816(acc[np * 2],     a0, a1, a2, a3, b0, b1);
                mma16816(acc[np * 2 + 1], a0, a1, a2, a3, b2, b3);
            }
        }
        __syncthreads();
        cur = nxt;
    }

    // epilogue: write h16, compute e_l/e_r (fp32), block emax
    const int crow = w * 16 + (lane >> 2);
    const int ccol = (lane & 3) * 2;
    __half2* hp16 = (__half2*)(g_h16 + ((size_t)head * NROWS + r0) * HID);
    const float* ah = a + head * 2 * HID;
    float pl0 = 0.f, pr0 = 0.f, pl1 = 0.f, pr1 = 0.f;
    #pragma unroll
    for (int nt = 0; nt < 8; nt++) {
        int c = nt * 8 + ccol;
        hp16[(crow * HID + c) >> 1]       = __floats2half2_rn(acc[nt][0], acc[nt][1]);
        hp16[((crow + 8) * HID + c) >> 1] = __floats2half2_rn(acc[nt][2], acc[nt][3]);
        float al0 = ah[c], al1 = ah[c + 1];
        float ar0 = ah[HID + c], ar1 = ah[HID + c + 1];
        pl0 += acc[nt][0] * al0 + acc[nt][1] * al1;
        pr0 += acc[nt][0] * ar0 + acc[nt][1] * ar1;
        pl1 += acc[nt][2] * al0 + acc[nt][3] * al1;
        pr1 += acc[nt][2] * ar0 + acc[nt][3] * ar1;
    }
    #pragma unroll
    for (int off = 1; off <= 2; off <<= 1) {
        pl0 += __shfl_xor_sync(0xffffffffu, pl0, off);
        pr0 += __shfl_xor_sync(0xffffffffu, pr0, off);
        pl1 += __shfl_xor_sync(0xffffffffu, pl1, off);
        pr1 += __shfl_xor_sync(0xffffffffu, pr1, off);
    }
    if ((lane & 3) == 0) {
        g_el[head * NROWS + r0 + crow] = pl0;
        g_er[head * NROWS + r0 + crow] = pr0;
        erow[crow] = pr0;
        g_el[head * NROWS + r0 + crow + 8] = pl1;
        g_er[head * NROWS + r0 + crow + 8] = pr1;
        erow[crow + 8] = pr1;
    }
    __syncthreads();
    if (tid == 0) {
        float m = erow[0];
        #pragma unroll
        for (int i = 1; i < 64; i++) m = fmaxf(m, erow[i]);
        atomicMax(&g_emax_u[layer * 4 + head], f2ord(m));
    }
}

// ---------------- 4. fused attention (unchanged core; fp16 activation output) ----------------
__global__ __launch_bounds__(128, 3) void attn_kernel(int layer, int doElu, int partial) {
    const int head = blockIdx.y;
    const int r0b = blockIdx.x * BRR;
    const int z = blockIdx.z;
    const int msplit = gridDim.z;
    const int mlen = NROWS / msplit;
    const int mstart = z * mlen;
    const int tid = threadIdx.x;
    const int lane = tid & 31, w = tid >> 5;

    __shared__ __align__(16) __half hsB[3][BM * HBP];  // triple-buffered h tile
    __shared__ __align__(16) float2 bd[4096];          // per-column (B, D)

    const float emax = ord2f(g_emax_u[layer * 4 + head]);
    for (int i = tid; i < mlen; i += 128) {
        float t = g_er[head * NROWS + mstart + i] - emax;
        bd[i] = make_float2(__expf(t), __expf(ALPHA * t));
    }

    const int rq = lane >> 2;
    const int c2 = (lane & 3) * 2;
    unsigned long long AC[2];
    float dacc[2];
    const unsigned* awp[2];
    #pragma unroll
    for (int i = 0; i < 2; i++) {
        int rowi = w * 16 + rq + i * 8;
        float el = g_el[head * NROWS + r0b + rowi];
        float s0 = el + emax;
        float M = fmaxf(s0, ALPHA * s0);
        AC[i] = packAC(__expf(s0 - M), __expf(ALPHA * s0 - M));
        dacc[i] = 0.f;
        awp[i] = g_adjbits + (size_t)(r0b + rowi) * NW;
    }

    float acc[8][4];
    #pragma unroll
    for (int nt = 0; nt < 8; nt++)
        #pragma unroll
        for (int c = 0; c < 4; c++) acc[nt][c] = 0.f;

    const __half* hb16 = g_h16 + (size_t)head * NROWS * HID;

    const int grp = lane >> 3, li = lane & 7;
    const unsigned hbS = (unsigned)__cvta_generic_to_shared(
        &hsB[0][((grp & 1) * 8 + li) * HBP + (grp >> 1) * 8]);

    int srow[4], sc8[4];
    unsigned sdst[4];
    const unsigned hsBS = (unsigned)__cvta_generic_to_shared(&hsB[0][0]);
    #pragma unroll
    for (int i = 0; i < 4; i++) {
        int idx = tid + i * 128;
        srow[i] = idx >> 3;
        sc8[i] = (idx & 7) * 8;
        sdst[i] = hsBS + (unsigned)((srow[i] * HBP + sc8[i]) * 2);
    }

    const int NCHUNK = mlen / BM;
    #pragma unroll
    for (int i = 0; i < 4; i++)
        cpasync16(sdst[i], &hb16[(size_t)(mstart + srow[i]) * HID + sc8[i]]);
    asm volatile("cp.async.commit_group;" ::: "memory");

    __syncthreads();   // bd ready

    int cur = 0;
    for (int ci = 0; ci < NCHUNK; ci++) {
        const int m0 = mstart + ci * BM;
        const int nxt = (cur == 2) ? 0 : cur + 1;
        if (ci + 1 < NCHUNK) {
            #pragma unroll
            for (int i = 0; i < 4; i++)
                cpasync16(sdst[i] + (unsigned)(nxt * BUFBYTES),
                          &hb16[(size_t)(m0 + BM + srow[i]) * HID + sc8[i]]);
        }
        asm volatile("cp.async.commit_group;" ::: "memory");
        uint2 aj[2];
        #pragma unroll
        for (int i = 0; i < 2; i++) aj[i] = *(const uint2*)(awp[i] + (m0 >> 5));
        asm volatile("cp.async.wait_group 1;" ::: "memory");
        __syncthreads();

        const float4* bd4 = (const float4*)(bd + (m0 - mstart));
        const unsigned hbC = hbS + (unsigned)(cur * BUFBYTES);
        #pragma unroll
        for (int ks = 0; ks < 4; ks++) {
            float4 q0 = bd4[ks * 8 + (lane & 3)];
            float4 q1 = bd4[ks * 8 + 4 + (lane & 3)];
            unsigned afr[4];
            #pragma unroll
            for (int i = 0; i < 2; i++) {
                unsigned wrd = (ks < 2) ? aj[i].x : aj[i].y;
                int sh = (ks & 1) * 16 + c2;
                float2 u0 = mul2(AC[i], *(const unsigned long long*)&q0.x);
                float2 u1 = mul2(AC[i], *(const unsigned long long*)&q0.z);
                float2 u2 = mul2(AC[i], *(const unsigned long long*)&q1.x);
                float2 u3 = mul2(AC[i], *(const unsigned long long*)&q1.z);
                float p0 = ((wrd >> sh) & 1u)       ? fmaxf(u0.x, u0.y) : 0.f;
                float p1 = ((wrd >> (sh + 1)) & 1u) ? fmaxf(u1.x, u1.y) : 0.f;
                float p2 = ((wrd >> (sh + 8)) & 1u) ? fmaxf(u2.x, u2.y) : 0.f;
                float p3 = ((wrd >> (sh + 9)) & 1u) ? fmaxf(u3.x, u3.y) : 0.f;
                dacc[i] += (p0 + p1) + (p2 + p3);
                __half2 hlo = __floats2half2_rn(p0, p1);
                __half2 hhi = __floats2half2_rn(p2, p3);
                afr[i]     = *(unsigned*)&hlo;
                afr[2 + i] = *(unsigned*)&hhi;
            }
            #pragma unroll
            for (int np = 0; np < 4; np++) {
                unsigned b0, b1, b2, b3;
                asm volatile("ldmatrix.sync.aligned.m8n8.x4.trans.shared.b16 {%0,%1,%2,%3}, [%4];"
                             : "=r"(b0), "=r"(b1), "=r"(b2), "=r"(b3)
                             : "r"(hbC + ks * (16 * HBP * 2) + np * 32));
                mma16816(acc[np * 2],     afr[0], afr[1], afr[2], afr[3], b0, b1);
                mma16816(acc[np * 2 + 1], afr[0], afr[1], afr[2], afr[3], b2, b3);
            }
        }
        cur = nxt;
    }

    #pragma unroll
    for (int i = 0; i < 2; i++) {
        dacc[i] += __shfl_xor_sync(0xffffffffu, dacc[i], 1);
        dacc[i] += __shfl_xor_sync(0xffffffffu, dacc[i], 2);
    }

    const int crow = w * 16 + (lane >> 2);
    const int ccol = (lane & 3) * 2;

    if (!partial) {
        const float inv0 = 1.0f / dacc[0];
        const float inv1 = 1.0f / dacc[1];
        #pragma unroll
        for (int nt = 0; nt < 8; nt++) {
            float v0 = acc[nt][0] * inv0, v1 = acc[nt][1] * inv0;
            float v2 = acc[nt][2] * inv1, v3 = acc[nt][3] * inv1;
            if (doElu) {
                v0 = (v0 > 0.f) ? v0 : expm1f(v0);
                v1 = (v1 > 0.f) ? v1 : expm1f(v1);
                v2 = (v2 > 0.f) ? v2 : expm1f(v2);
                v3 = (v3 > 0.f) ? v3 : expm1f(v3);
            }
            int c = head * HID + nt * 8 + ccol;
            *(__half2*)&g_buf16[(size_t)(r0b + crow) * 256 + c] = __floats2half2_rn(v0, v1);
            *(__half2*)&g_buf16[(size_t)(r0b + crow + 8) * 256 + c] = __floats2half2_rn(v2, v3);
        }
    } else {
        const int pidx = (blockIdx.x * gridDim.y + head) * msplit + z;
        if ((lane & 3) == 0) {
            #pragma unroll
            for (int i = 0; i < 2; i++)
                g_pden[(size_t)pidx * BRR + w * 16 + rq + i * 8] = dacc[i];
        }
        float* np_ = g_pnum + (size_t)pidx * (BRR * HID);
        #pragma unroll
        for (int nt = 0; nt < 8; nt++) {
            *(float2*)&np_[(size_t)crow * HID + nt * 8 + ccol] =
                make_float2(acc[nt][0], acc[nt][1]);
            *(float2*)&np_[(size_t)(crow + 8) * HID + nt * 8 + ccol] =
                make_float2(acc[nt][2], acc[nt][3]);
        }
    }
}

// ---------------- 5. combine layer-2 partials -> out ----------------
__global__ void combine_kernel(float* __restrict__ dest, int msplit) {
    const int rb = blockIdx.x;
    const int base = rb * msplit;
    for (int idx = threadIdx.x; idx < BRR * HID; idx += 256) {
        int row = idx >> 6;
        float num = 0.f, den = 0.f;
        for (int zz = 0; zz < msplit; zz++) {
            num += g_pnum[(size_t)(base + zz) * (BRR * HID) + idx];
            den += g_pden[(size_t)(base + zz) * BRR + row];
        }
        dest[(size_t)(rb * BRR + row) * HID + (idx & 63)] = num / den;
    }
}

// ---------------- launch ----------------
extern "C" void kernel_launch(void* const* d_in, const int* in_sizes, int n_in,
                              void* d_out, int out_size) {
    const float* x   = (const float*)d_in[0];
    const int*   adj = (const int*)d_in[1];
    const float* W0  = (const float*)d_in[2];
    const float* a0  = (const float*)d_in[3];
    const float* W1  = (const float*)d_in[4];
    const float* a1  = (const float*)d_in[5];
    const float* W2  = (const float*)d_in[6];
    const float* a2  = (const float*)d_in[7];
    float* out = (float*)d_out;

    __half *d_x16, *d_W16, *d_buf16;
    cudaGetSymbolAddress((void**)&d_x16, g_x16);
    cudaGetSymbolAddress((void**)&d_W16, g_W16);
    cudaGetSymbolAddress((void**)&d_buf16, g_buf16);

    pack_adj_kernel<<<NROWS, 128>>>(adj);
    convert_kernel<<<512, 256>>>(x, W0, W1, W2);

    // layer 0: D=128, H=4
    gemm16_kernel<<<dim3(64, 4), 128>>>(d_x16, d_W16 + W0OFF, a0, 128, 0);
    attn_kernel<<<dim3(64, 4, 1), 128>>>(0, 1, 0);

    // layer 1: D=256, H=4
    gemm16_kernel<<<dim3(64, 4), 128>>>(d_buf16, d_W16 + W1OFF, a1, 256, 1);
    attn_kernel<<<dim3(64, 4, 1), 128>>>(1, 1, 0);

    // layer 2: D=256, H=1, msplit=4 + combine
    gemm16_kernel<<<dim3(64, 1), 128>>>(d_buf16, d_W16 + W2OFF, a2, 256, 2);
    attn_kernel<<<dim3(64, 1, 4), 128>>>(2, 0, 1);
    combine_kernel<<<64, 256>>>(out, 4);
}